// round 11
// baseline (speedup 1.0000x reference)
#include <cuda_runtime.h>
#include <cuda_fp16.h>
#include <math.h>

#define BB 8
#define CC 256
#define HH 128
#define WW 128
#define NN (HH*WW)          // 16384
#define NPOS 256
#define NHARD 96
#define NRAND 32
#define TEMP_INV (1.0f/0.07f)

#define ROWQ 33             // quads (16B units) per padded fp16 row (264 halves)

// ---------------- scratch (static device globals; no allocation) ------------
__device__ __half g_rgbTh[BB*NN*CC];    // normalized rgb (fp16), [b][px][ch]
__device__ float g_acc[3];              // loss_sum, mask_sum, correct_sum
__device__ unsigned g_done;

// ---------------- mma/ldmatrix helpers ---------------------------------------
__device__ __forceinline__ void ldmx4(unsigned* r, unsigned addr) {
    asm volatile("ldmatrix.sync.aligned.m8n8.x4.shared.b16 {%0,%1,%2,%3}, [%4];"
                 : "=r"(r[0]), "=r"(r[1]), "=r"(r[2]), "=r"(r[3]) : "r"(addr));
}
__device__ __forceinline__ void ldmx2(unsigned* r, unsigned addr) {
    asm volatile("ldmatrix.sync.aligned.m8n8.x2.shared.b16 {%0,%1}, [%2];"
                 : "=r"(r[0]), "=r"(r[1]) : "r"(addr));
}
__device__ __forceinline__ void mma16816(float* d, const unsigned* a, const unsigned* b) {
    asm volatile(
        "mma.sync.aligned.m16n8k16.row.col.f32.f16.f16.f32 "
        "{%0,%1,%2,%3}, {%4,%5,%6,%7}, {%8,%9}, {%0,%1,%2,%3};"
        : "+f"(d[0]), "+f"(d[1]), "+f"(d[2]), "+f"(d[3])
        : "r"(a[0]), "r"(a[1]), "r"(a[2]), "r"(a[3]),
          "r"(b[0]), "r"(b[1]));
}

// ---------------- kernel 1: normalize + transpose (conflict-free) ------------
__global__ __launch_bounds__(256) void k_norm_t(const float* __restrict__ in) {
    __shared__ float s_tile[CC*33];
    __shared__ float s_red[8*33];
    __shared__ float s_inv[32];
    __shared__ __half s_half[32*ROWQ*8];   // 32 px * 264 halves (16.9 KB)
    const int tid = threadIdx.x;
    const int tx = tid & 31;        // pixel in tile
    const int ty = tid >> 5;        // warp id / channel subset
    const int blocksPerBatch = NN/32;
    const int b  = blockIdx.x / blocksPerBatch;
    const int n0 = (blockIdx.x % blocksPerBatch) * 32;

    if (blockIdx.x == 0 && tid < 3) g_acc[tid] = 0.0f;
    if (blockIdx.x == 0 && tid == 3) g_done = 0;

    const float* src = in + b*CC*NN + n0;
    float ss = 0.0f;
    #pragma unroll 8
    for (int i = 0; i < 32; i++) {
        int c = i*8 + ty;
        float v = src[c*NN + tx];
        s_tile[c*33 + tx] = v;
        ss += v*v;
    }
    s_red[ty*33 + tx] = ss;
    __syncthreads();
    if (ty == 0) {
        float t = 0.0f;
        #pragma unroll
        for (int j = 0; j < 8; j++) t += s_red[j*33 + tx];
        s_inv[tx] = 1.0f / fmaxf(sqrtf(t), 1e-12f);
    }
    __syncthreads();

    {
        const int px = tx;
        float inv = s_inv[px];
        uint4* hrow = reinterpret_cast<uint4*>(s_half) + px*ROWQ;
        #pragma unroll
        for (int cc2 = 0; cc2 < 4; cc2++) {
            int ch = ty*4 + cc2;
            float v[8];
            #pragma unroll
            for (int j = 0; j < 8; j++) v[j] = s_tile[(ch*8 + j)*33 + px] * inv;
            uint4 q;
            __half2 h;
            h = __floats2half2_rn(v[0], v[1]); q.x = *reinterpret_cast<unsigned*>(&h);
            h = __floats2half2_rn(v[2], v[3]); q.y = *reinterpret_cast<unsigned*>(&h);
            h = __floats2half2_rn(v[4], v[5]); q.z = *reinterpret_cast<unsigned*>(&h);
            h = __floats2half2_rn(v[6], v[7]); q.w = *reinterpret_cast<unsigned*>(&h);
            hrow[ch] = q;
        }
    }
    __syncthreads();

    {
        uint4* dst = reinterpret_cast<uint4*>(g_rgbTh + (size_t)(b*NN + n0)*CC);
        const uint4* srcq = reinterpret_cast<const uint4*>(s_half);
        const int cb = tid & 31;
        const int pq = tid >> 5;
        #pragma unroll
        for (int it = 0; it < 4; it++) {
            int px = it*8 + pq;
            dst[px*(CC/8) + cb] = srcq[px*ROWQ + cb];
        }
    }
}

// ---------------- kernel 2: fully fused main pass -----------------------------
__device__ __forceinline__ int corner_idx(int xx, int yy, float& w) {
    bool v = (xx >= 0) & (xx < WW) & (yy >= 0) & (yy < HH);
    if (!v) w = 0.0f;
    int cx = min(max(xx, 0), WW-1);
    int cy = min(max(yy, 0), HH-1);
    return cy*WW + cx;
}

__global__ __launch_bounds__(256) void k_main(const float* __restrict__ dep,
                                              const float* __restrict__ proj,
                                              const int*   __restrict__ rand_idx,
                                              const int*   __restrict__ offu,
                                              const int*   __restrict__ offv,
                                              const float* __restrict__ valid,
                                              float* __restrict__ out) {
    extern __shared__ float sm[];
    __half* s_depH  = reinterpret_cast<__half*>(sm);     // hi: 64*264 halves
    __half* s_depL  = s_depH + 64*ROWQ*8;                // lo: 64*264 halves
    __half* s_randH = s_depL + 64*ROWQ*8;                // 32*264 halves
    float*  s_sim   = reinterpret_cast<float*>(s_randH + 32*ROWQ*8); // 32*65
    float*  s_pos   = s_sim + NRAND*65;                  // 64
    float*  s_inv   = s_pos + 64;                        // 64
    float*  s_red   = s_inv + 64;                        // 4*65
    float*  s_hard  = s_red + 4*65;                      // 8*96

    const int tid = threadIdx.x;
    const int tx  = tid & 31;
    const int ty  = tid >> 5;                  // warp id 0..7
    const int blocksPerBatch = NN/64;
    const int b  = blockIdx.x / blocksPerBatch;
    const int n0 = (blockIdx.x % blocksPerBatch) * 64;

    // ---- stage dep tile split fp16 hi/lo + partial norms (fp32) ----
    {
        const int px = tid & 63;
        const int cg = tid >> 6;
        const float* dsrc = dep + b*CC*NN + n0 + px;
        float ss = 0.0f;
        uint4* hrow = reinterpret_cast<uint4*>(s_depH) + px*ROWQ;
        uint4* lrow = reinterpret_cast<uint4*>(s_depL) + px*ROWQ;
        #pragma unroll
        for (int j = 0; j < 8; j++) {
            int chunk = cg*8 + j;
            float v[8];
            __half hi[8], lo[8];
            #pragma unroll
            for (int t = 0; t < 8; t++) {
                v[t] = dsrc[(chunk*8 + t)*NN];
                ss += v[t]*v[t];
                hi[t] = __float2half_rn(v[t]);
                lo[t] = __float2half_rn(v[t] - __half2float(hi[t]));
            }
            uint4 qh, ql;
            __half2 h;
            h = __halves2half2(hi[0], hi[1]); qh.x = *reinterpret_cast<unsigned*>(&h);
            h = __halves2half2(hi[2], hi[3]); qh.y = *reinterpret_cast<unsigned*>(&h);
            h = __halves2half2(hi[4], hi[5]); qh.z = *reinterpret_cast<unsigned*>(&h);
            h = __halves2half2(hi[6], hi[7]); qh.w = *reinterpret_cast<unsigned*>(&h);
            h = __halves2half2(lo[0], lo[1]); ql.x = *reinterpret_cast<unsigned*>(&h);
            h = __halves2half2(lo[2], lo[3]); ql.y = *reinterpret_cast<unsigned*>(&h);
            h = __halves2half2(lo[4], lo[5]); ql.z = *reinterpret_cast<unsigned*>(&h);
            h = __halves2half2(lo[6], lo[7]); ql.w = *reinterpret_cast<unsigned*>(&h);
            hrow[chunk] = qh;
            lrow[chunk] = ql;
        }
        s_red[cg*65 + px] = ss;
    }
    // ---- stage rand vectors (fp16 rows, padded) ----
    {
        int k = tid >> 3, part = tid & 7;
        int ridx = rand_idx[b*NRAND + k];
        const uint4* row = reinterpret_cast<const uint4*>(g_rgbTh + (size_t)(b*NN + ridx)*CC);
        uint4* drow = reinterpret_cast<uint4*>(s_randH) + k*ROWQ;
        #pragma unroll
        for (int i = 0; i < 4; i++) {
            int chunk = part + 8*i;
            drow[chunk] = row[chunk];
        }
    }
    __syncthreads();
    if (tid < 64) {
        float t = s_red[tid] + s_red[65 + tid] + s_red[2*65 + tid] + s_red[3*65 + tid];
        s_inv[tid] = 1.0f / fmaxf(sqrtf(t), 1e-12f);
    }
    __syncthreads();

    // ---- phase 3: rand GEMM on tensor cores, hi+lo split dep ----
    {
        unsigned aHBase = (unsigned)__cvta_generic_to_shared(s_depH);
        unsigned aLBase = (unsigned)__cvta_generic_to_shared(s_depL);
        unsigned bBase  = (unsigned)__cvta_generic_to_shared(s_randH);
        const int pxb = (ty & 3) * 16;
        const int kb0 = (ty >> 2) * 16;
        const unsigned aRow = (unsigned)(pxb + (tx & 15)) * ROWQ + (unsigned)(tx >> 4);
        const unsigned bRow0 = (unsigned)(kb0 + (tx & 7)) * ROWQ + (unsigned)((tx >> 3) & 1);
        const unsigned bRow1 = bRow0 + 8u*ROWQ;
        float d0[4] = {0,0,0,0}, d1[4] = {0,0,0,0};
        #pragma unroll
        for (int kk = 0; kk < 16; kk++) {
            unsigned ah[4], al[4], b0r[2], b1r[2];
            ldmx4(ah,  aHBase + (aRow  + 2*kk) * 16);
            ldmx4(al,  aLBase + (aRow  + 2*kk) * 16);
            ldmx2(b0r, bBase  + (bRow0 + 2*kk) * 16);
            ldmx2(b1r, bBase  + (bRow1 + 2*kk) * 16);
            mma16816(d0, ah, b0r);
            mma16816(d0, al, b0r);
            mma16816(d1, ah, b1r);
            mma16816(d1, al, b1r);
        }
        int pxl = pxb + (tx >> 2);
        int kl  = (tx & 3) * 2;
        s_sim[(kb0 + kl + 0)*65 + pxl]     = d0[0];
        s_sim[(kb0 + kl + 1)*65 + pxl]     = d0[1];
        s_sim[(kb0 + kl + 0)*65 + pxl + 8] = d0[2];
        s_sim[(kb0 + kl + 1)*65 + pxl + 8] = d0[3];
        s_sim[(kb0 + 8 + kl + 0)*65 + pxl]     = d1[0];
        s_sim[(kb0 + 8 + kl + 1)*65 + pxl]     = d1[1];
        s_sim[(kb0 + 8 + kl + 0)*65 + pxl + 8] = d1[2];
        s_sim[(kb0 + 8 + kl + 1)*65 + pxl + 8] = d1[3];
    }

    // ---- phase 2: pos_sim (warp handles 8 pixels), dep = hi + lo ----
    const float* projU = proj + b*2*NN;
    const float* projV = projU + NN;
    const uint4* depHQ = reinterpret_cast<const uint4*>(s_depH);
    const uint4* depLQ = reinterpret_cast<const uint4*>(s_depL);
    #pragma unroll
    for (int q = 0; q < 8; q++) {
        int px = ty*8 + q;
        int n  = n0 + px;
        float pu = projU[n], pv = projV[n];
        float x0f = floorf(pu), y0f = floorf(pv);
        float wx = pu - x0f, wy = pv - y0f;
        int x0 = (int)x0f, y0 = (int)y0f;
        float w00 = (1.0f-wx)*(1.0f-wy), w10 = wx*(1.0f-wy);
        float w01 = (1.0f-wx)*wy,        w11 = wx*wy;
        int i00 = corner_idx(x0,   y0,   w00);
        int i10 = corner_idx(x0+1, y0,   w10);
        int i01 = corner_idx(x0,   y0+1, w01);
        int i11 = corner_idx(x0+1, y0+1, w11);
        const uint4* r00 = reinterpret_cast<const uint4*>(g_rgbTh + (size_t)(b*NN + i00)*CC);
        const uint4* r10 = reinterpret_cast<const uint4*>(g_rgbTh + (size_t)(b*NN + i10)*CC);
        const uint4* r01 = reinterpret_cast<const uint4*>(g_rgbTh + (size_t)(b*NN + i01)*CC);
        const uint4* r11 = reinterpret_cast<const uint4*>(g_rgbTh + (size_t)(b*NN + i11)*CC);
        uint4 dqh = depHQ[px*ROWQ + tx];
        uint4 dql = depLQ[px*ROWQ + tx];
        uint4 q00 = r00[tx], q10 = r10[tx], q01 = r01[tx], q11 = r11[tx];
        float pacc = 0.0f;
        const unsigned* duh = &dqh.x;
        const unsigned* dul = &dql.x;
        const unsigned* u00 = &q00.x;
        const unsigned* u10 = &q10.x;
        const unsigned* u01 = &q01.x;
        const unsigned* u11 = &q11.x;
        #pragma unroll
        for (int j = 0; j < 4; j++) {
            float2 dh = __half22float2(*reinterpret_cast<const __half2*>(&duh[j]));
            float2 dl = __half22float2(*reinterpret_cast<const __half2*>(&dul[j]));
            float dx = dh.x + dl.x, dy = dh.y + dl.y;
            float2 a00 = __half22float2(*reinterpret_cast<const __half2*>(&u00[j]));
            float2 a10 = __half22float2(*reinterpret_cast<const __half2*>(&u10[j]));
            float2 a01 = __half22float2(*reinterpret_cast<const __half2*>(&u01[j]));
            float2 a11 = __half22float2(*reinterpret_cast<const __half2*>(&u11[j]));
            pacc += dx*(w00*a00.x + w10*a10.x + w01*a01.x + w11*a11.x);
            pacc += dy*(w00*a00.y + w10*a10.y + w01*a01.y + w11*a11.y);
        }
        #pragma unroll
        for (int o = 16; o; o >>= 1) pacc += __shfl_xor_sync(0xffffffffu, pacc, o);
        if (tx == 0) s_pos[px] = pacc;
    }
    __syncthreads();

    // ---- phase 4: logsumexp / max; grid pixels stashed in registers ----
    const int v_row = n0 >> 7;
    const int u0 = n0 & 127;
    const bool gridRow = ((v_row & 7) == 0);
    float wl = 0.0f, wm = 0.0f, wc = 0.0f;
    float pos0 = 0.0f, lse0 = 0.0f, mx0 = 0.0f;
    #pragma unroll
    for (int q = 0; q < 8; q++) {
        int px = ty*8 + q;
        float scale = s_inv[px] * TEMP_INV;
        float pos = s_pos[px] * scale;
        float v = s_sim[tx*65 + px] * scale;
        float mneg = v;
        #pragma unroll
        for (int o = 16; o; o >>= 1) mneg = fmaxf(mneg, __shfl_xor_sync(0xffffffffu, mneg, o));
        float m = fmaxf(pos, mneg);
        float e = expf(v - m);
        #pragma unroll
        for (int o = 16; o; o >>= 1) e += __shfl_xor_sync(0xffffffffu, e, o);
        if (tx == 0) {
            float lse = m + logf(e + expf(pos - m));
            if (gridRow && q == 0) {
                pos0 = pos; lse0 = lse; mx0 = mneg;   // merge after hard phase
            } else {
                float mask = valid[b*NN + n0 + px];
                wl += (lse - pos) * mask;
                wm += mask;
                wc += (pos > mneg && mask > 0.5f) ? 1.0f : 0.0f;
            }
        }
    }

    // ---- phase 5: hard negatives (grid-row blocks only; warp = grid point) --
    if (gridRow) {
        const int px = ty*8;
        const int ng = n0 + px;
        const int p = ((v_row >> 3) << 4) + ((u0 + px) >> 3);
        const float sc = s_inv[px] * TEMP_INV;

        // lane's 8 dep channels (fp32 = hi + lo)
        uint4 dqh = depHQ[px*ROWQ + tx];
        uint4 dql = depLQ[px*ROWQ + tx];
        float d[8];
        {
            const unsigned* duh = &dqh.x;
            const unsigned* dul = &dql.x;
            #pragma unroll
            for (int j = 0; j < 4; j++) {
                float2 fh = __half22float2(*reinterpret_cast<const __half2*>(&duh[j]));
                float2 fl = __half22float2(*reinterpret_cast<const __half2*>(&dul[j]));
                d[2*j]   = fh.x + fl.x;
                d[2*j+1] = fh.y + fl.y;
            }
        }
        float pu = projU[ng], pv = projV[ng];
        int posu = (int)fminf(fmaxf(pu, 0.0f), (float)(WW-1));
        int posv = (int)fminf(fmaxf(pv, 0.0f), (float)(HH-1));

        float* hslot = s_hard + ty*96;
        #pragma unroll 2
        for (int g = 0; g < 24; g++) {
            const uint4* r[4];
            #pragma unroll
            for (int j = 0; j < 4; j++) {
                int h = g*4 + j;
                int ou = offu[(b*NHARD + h)*NPOS + p];
                int ov = offv[(b*NHARD + h)*NPOS + p];
                if (ou == 0 && ov == 0) ou = 1;
                int hu = min(max(posu + ou, 0), WW-1);
                int hv = min(max(posv + ov, 0), HH-1);
                r[j] = reinterpret_cast<const uint4*>(g_rgbTh + (size_t)(b*NN + hv*WW + hu)*CC);
            }
            uint4 qr[4];
            #pragma unroll
            for (int j = 0; j < 4; j++) qr[j] = r[j][tx];
            float a[4];
            #pragma unroll
            for (int j = 0; j < 4; j++) {
                const unsigned* u = &qr[j].x;
                float s = 0.0f;
                #pragma unroll
                for (int c2 = 0; c2 < 4; c2++) {
                    float2 f = __half22float2(*reinterpret_cast<const __half2*>(&u[c2]));
                    s += d[2*c2]*f.x + d[2*c2+1]*f.y;
                }
                a[j] = s;
            }
            #pragma unroll
            for (int o = 16; o; o >>= 1) {
                a[0] += __shfl_xor_sync(0xffffffffu, a[0], o);
                a[1] += __shfl_xor_sync(0xffffffffu, a[1], o);
                a[2] += __shfl_xor_sync(0xffffffffu, a[2], o);
                a[3] += __shfl_xor_sync(0xffffffffu, a[3], o);
            }
            if (tx == 0) {
                hslot[g*4+0] = a[0] * sc;
                hslot[g*4+1] = a[1] * sc;
                hslot[g*4+2] = a[2] * sc;
                hslot[g*4+3] = a[3] * sc;
            }
        }
        __syncwarp();

        // lane-parallel 96-wide logsumexp / max
        float v0 = hslot[tx];
        float v1 = hslot[tx + 32];
        float v2 = hslot[tx + 64];
        float m = fmaxf(fmaxf(v0, v1), v2);
        #pragma unroll
        for (int o = 16; o; o >>= 1) m = fmaxf(m, __shfl_xor_sync(0xffffffffu, m, o));
        float se = expf(v0 - m) + expf(v1 - m) + expf(v2 - m);
        #pragma unroll
        for (int o = 16; o; o >>= 1) se += __shfl_xor_sync(0xffffffffu, se, o);
        if (tx == 0) {
            float lse_h = m + logf(se);
            float mm = fmaxf(lse0, lse_h);
            float lse = mm + logf(expf(lse0 - mm) + expf(lse_h - mm));
            float mx = fmaxf(mx0, m);
            float mask = valid[b*NN + ng];
            wl += (lse - pos0) * mask;
            wm += mask;
            wc += (pos0 > mx && mask > 0.5f) ? 1.0f : 0.0f;
        }
    }
    __syncthreads();

    // ---- block reduction + completion-counted epilogue ----
    if (tx == 0) {
        s_red[ty] = wl;
        s_red[8 + ty] = wm;
        s_red[16 + ty] = wc;
    }
    __syncthreads();
    if (tid == 0) {
        float a = 0.f, b2 = 0.f, c2 = 0.f;
        #pragma unroll
        for (int j = 0; j < 8; j++) { a += s_red[j]; b2 += s_red[8+j]; c2 += s_red[16+j]; }
        atomicAdd(&g_acc[0], a);
        atomicAdd(&g_acc[1], b2);
        atomicAdd(&g_acc[2], c2);
        __threadfence();
        unsigned t = atomicAdd(&g_done, 1u);
        if (t == gridDim.x - 1u) {
            __threadfence();
            float denom = fmaxf(g_acc[1], 1.0f);
            out[0] = g_acc[0] / denom;
            out[1] = g_acc[2] / denom * 100.0f;
        }
    }
}

// ---------------- launch -------------------------------------------------------
extern "C" void kernel_launch(void* const* d_in, const int* in_sizes, int n_in,
                              void* d_out, int out_size) {
    const float* rgb   = (const float*)d_in[0];
    const float* dep   = (const float*)d_in[1];
    const float* proj  = (const float*)d_in[2];
    const float* valid = (const float*)d_in[3];
    const int*   ridx  = (const int*)d_in[4];
    const int*   offu  = (const int*)d_in[5];
    const int*   offv  = (const int*)d_in[6];
    float* out = (float*)d_out;

    const int smem_main = 64*ROWQ*16*2 + 32*ROWQ*16
                        + (NRAND*65 + 64 + 64 + 4*65 + 8*96) * (int)sizeof(float);
    cudaFuncSetAttribute(k_main, cudaFuncAttributeMaxDynamicSharedMemorySize, smem_main);

    k_norm_t<<<BB*NN/32, 256>>>(rgb);
    k_main<<<BB*NN/64, 256, smem_main>>>(dep, proj, ridx, offu, offv, valid, out);
}

// round 12
// speedup vs baseline: 1.3400x; 1.3400x over previous
#include <cuda_runtime.h>
#include <cuda_fp16.h>
#include <math.h>

#define BB 8
#define CC 256
#define HH 128
#define WW 128
#define NN (HH*WW)          // 16384
#define NPOS 256
#define NHARD 96
#define NRAND 32
#define TEMP_INV (1.0f/0.07f)

#define ROWQ 33             // quads (16B units) per padded fp16 row (264 halves)
#define TSTR 36             // fp32 tile row stride (floats), float4-aligned

// ---------------- scratch (static device globals; no allocation) ------------
__device__ __half g_rgbTh[BB*NN*CC];    // normalized rgb (fp16), [b][px][ch]
__device__ float g_depGrid[BB*NPOS*CC]; // normalized*TEMP_INV dep at grid pts
__device__ float g_posG[BB*NPOS];       // pos_sim at grid points
__device__ float g_lseG[BB*NPOS];       // base lse at grid points
__device__ float g_mxG[BB*NPOS];        // rand max at grid points
__device__ float g_acc[3];              // loss_sum, mask_sum, correct_sum
__device__ unsigned g_done;

// ---------------- mma/ldmatrix helpers ---------------------------------------
__device__ __forceinline__ void ldmx4(unsigned* r, unsigned addr) {
    asm volatile("ldmatrix.sync.aligned.m8n8.x4.shared.b16 {%0,%1,%2,%3}, [%4];"
                 : "=r"(r[0]), "=r"(r[1]), "=r"(r[2]), "=r"(r[3]) : "r"(addr));
}
__device__ __forceinline__ void ldmx2(unsigned* r, unsigned addr) {
    asm volatile("ldmatrix.sync.aligned.m8n8.x2.shared.b16 {%0,%1}, [%2];"
                 : "=r"(r[0]), "=r"(r[1]) : "r"(addr));
}
__device__ __forceinline__ void mma16816(float* d, const unsigned* a, const unsigned* b) {
    asm volatile(
        "mma.sync.aligned.m16n8k16.row.col.f32.f16.f16.f32 "
        "{%0,%1,%2,%3}, {%4,%5,%6,%7}, {%8,%9}, {%0,%1,%2,%3};"
        : "+f"(d[0]), "+f"(d[1]), "+f"(d[2]), "+f"(d[3])
        : "r"(a[0]), "r"(a[1]), "r"(a[2]), "r"(a[3]),
          "r"(b[0]), "r"(b[1]));
}

// ---------------- kernel 1: normalize + transpose (float4 loads) -------------
__global__ __launch_bounds__(256) void k_norm_t(const float* __restrict__ in) {
    extern __shared__ float smn[];
    float*  s_tile = smn;                         // CC * 36 floats
    float*  s_red  = s_tile + CC*TSTR;            // 8 * 36
    float*  s_inv  = s_red + 8*TSTR;              // 32
    __half* s_half = reinterpret_cast<__half*>(s_inv + 32);   // 32 * 264 halves

    const int tid = threadIdx.x;
    const int tx = tid & 31;
    const int ty = tid >> 5;
    const int blocksPerBatch = NN/32;
    const int b  = blockIdx.x / blocksPerBatch;
    const int n0 = (blockIdx.x % blocksPerBatch) * 32;

    if (blockIdx.x == 0 && tid < 3) g_acc[tid] = 0.0f;
    if (blockIdx.x == 0 && tid == 3) g_done = 0;

    // ---- phase A: float4 loads (4 px / thread) + fused sum-of-squares ----
    const float* src = in + b*CC*NN + n0;
    const int pxg = tid & 7;          // pixel group: pixels pxg*4..pxg*4+3
    const int c0  = tid >> 3;         // channel 0..31 within each pass
    float ss0 = 0.f, ss1 = 0.f, ss2 = 0.f, ss3 = 0.f;
    #pragma unroll
    for (int pass = 0; pass < 8; pass++) {
        int c = pass*32 + c0;
        float4 v = *reinterpret_cast<const float4*>(src + c*NN + pxg*4);
        *reinterpret_cast<float4*>(&s_tile[c*TSTR + pxg*4]) = v;
        ss0 += v.x*v.x; ss1 += v.y*v.y; ss2 += v.z*v.z; ss3 += v.w*v.w;
    }
    // combine the 4 c-values within each warp (lanes sharing pxg)
    #pragma unroll
    for (int o = 8; o <= 16; o <<= 1) {
        ss0 += __shfl_xor_sync(0xffffffffu, ss0, o);
        ss1 += __shfl_xor_sync(0xffffffffu, ss1, o);
        ss2 += __shfl_xor_sync(0xffffffffu, ss2, o);
        ss3 += __shfl_xor_sync(0xffffffffu, ss3, o);
    }
    if (tx < 8) {
        *reinterpret_cast<float4*>(&s_red[ty*TSTR + tx*4]) =
            make_float4(ss0, ss1, ss2, ss3);
    }
    __syncthreads();
    if (tid < 32) {
        float t = 0.0f;
        #pragma unroll
        for (int w = 0; w < 8; w++) t += s_red[w*TSTR + tid];
        s_inv[tid] = 1.0f / fmaxf(sqrtf(t), 1e-12f);
    }
    __syncthreads();

    // ---- phase B: scale + fp16 pack, lane = pixel (conflict-free) ----
    {
        const int px = tx;
        float inv = s_inv[px];
        uint4* hrow = reinterpret_cast<uint4*>(s_half) + px*ROWQ;
        #pragma unroll
        for (int cc2 = 0; cc2 < 4; cc2++) {
            int ch = ty*4 + cc2;
            float v[8];
            #pragma unroll
            for (int j = 0; j < 8; j++) v[j] = s_tile[(ch*8 + j)*TSTR + px] * inv;
            uint4 q;
            __half2 h;
            h = __floats2half2_rn(v[0], v[1]); q.x = *reinterpret_cast<unsigned*>(&h);
            h = __floats2half2_rn(v[2], v[3]); q.y = *reinterpret_cast<unsigned*>(&h);
            h = __floats2half2_rn(v[4], v[5]); q.z = *reinterpret_cast<unsigned*>(&h);
            h = __floats2half2_rn(v[6], v[7]); q.w = *reinterpret_cast<unsigned*>(&h);
            hrow[ch] = q;
        }
    }
    __syncthreads();

    // ---- phase C: coalesced uint4 copy smem -> global ----
    {
        uint4* dst = reinterpret_cast<uint4*>(g_rgbTh + (size_t)(b*NN + n0)*CC);
        const uint4* srcq = reinterpret_cast<const uint4*>(s_half);
        const int cb = tid & 31;
        const int pq = tid >> 5;
        #pragma unroll
        for (int it = 0; it < 4; it++) {
            int px = it*8 + pq;
            dst[px*(CC/8) + cb] = srcq[px*ROWQ + cb];
        }
    }
}

// ---------------- kernel 2: main pass + fused loss (non-grid pixels) ---------
__device__ __forceinline__ int corner_idx(int xx, int yy, float& w) {
    bool v = (xx >= 0) & (xx < WW) & (yy >= 0) & (yy < HH);
    if (!v) w = 0.0f;
    int cx = min(max(xx, 0), WW-1);
    int cy = min(max(yy, 0), HH-1);
    return cy*WW + cx;
}

__global__ __launch_bounds__(256) void k_main(const float* __restrict__ dep,
                                              const float* __restrict__ proj,
                                              const int*   __restrict__ rand_idx,
                                              const float* __restrict__ valid) {
    extern __shared__ float sm[];
    __half* s_depH  = reinterpret_cast<__half*>(sm);     // hi: 64*264 halves
    __half* s_depL  = s_depH + 64*ROWQ*8;                // lo: 64*264 halves
    __half* s_randH = s_depL + 64*ROWQ*8;                // 32*264 halves
    float*  s_sim   = reinterpret_cast<float*>(s_randH + 32*ROWQ*8); // 32*65
    float*  s_pos   = s_sim + NRAND*65;                  // 64
    float*  s_inv   = s_pos + 64;                        // 64
    float*  s_red   = s_inv + 64;                        // 4*65

    const int tid = threadIdx.x;
    const int tx  = tid & 31;
    const int ty  = tid >> 5;                  // warp id 0..7
    const int blocksPerBatch = NN/64;
    const int b  = blockIdx.x / blocksPerBatch;
    const int n0 = (blockIdx.x % blocksPerBatch) * 64;

    // ---- stage dep tile split fp16 hi/lo + partial norms (fp32) ----
    {
        const int px = tid & 63;
        const int cg = tid >> 6;
        const float* dsrc = dep + b*CC*NN + n0 + px;
        float ss = 0.0f;
        uint4* hrow = reinterpret_cast<uint4*>(s_depH) + px*ROWQ;
        uint4* lrow = reinterpret_cast<uint4*>(s_depL) + px*ROWQ;
        #pragma unroll
        for (int j = 0; j < 8; j++) {
            int chunk = cg*8 + j;
            float v[8];
            __half hi[8], lo[8];
            #pragma unroll
            for (int t = 0; t < 8; t++) {
                v[t] = dsrc[(chunk*8 + t)*NN];
                ss += v[t]*v[t];
                hi[t] = __float2half_rn(v[t]);
                lo[t] = __float2half_rn(v[t] - __half2float(hi[t]));
            }
            uint4 qh, ql;
            __half2 h;
            h = __halves2half2(hi[0], hi[1]); qh.x = *reinterpret_cast<unsigned*>(&h);
            h = __halves2half2(hi[2], hi[3]); qh.y = *reinterpret_cast<unsigned*>(&h);
            h = __halves2half2(hi[4], hi[5]); qh.z = *reinterpret_cast<unsigned*>(&h);
            h = __halves2half2(hi[6], hi[7]); qh.w = *reinterpret_cast<unsigned*>(&h);
            h = __halves2half2(lo[0], lo[1]); ql.x = *reinterpret_cast<unsigned*>(&h);
            h = __halves2half2(lo[2], lo[3]); ql.y = *reinterpret_cast<unsigned*>(&h);
            h = __halves2half2(lo[4], lo[5]); ql.z = *reinterpret_cast<unsigned*>(&h);
            h = __halves2half2(lo[6], lo[7]); ql.w = *reinterpret_cast<unsigned*>(&h);
            hrow[chunk] = qh;
            lrow[chunk] = ql;
        }
        s_red[cg*65 + px] = ss;
    }
    // ---- stage rand vectors (fp16 rows, padded) ----
    {
        int k = tid >> 3, part = tid & 7;
        int ridx = rand_idx[b*NRAND + k];
        const uint4* row = reinterpret_cast<const uint4*>(g_rgbTh + (size_t)(b*NN + ridx)*CC);
        uint4* drow = reinterpret_cast<uint4*>(s_randH) + k*ROWQ;
        #pragma unroll
        for (int i = 0; i < 4; i++) {
            int chunk = part + 8*i;
            drow[chunk] = row[chunk];
        }
    }
    __syncthreads();
    if (tid < 64) {
        float t = s_red[tid] + s_red[65 + tid] + s_red[2*65 + tid] + s_red[3*65 + tid];
        s_inv[tid] = 1.0f / fmaxf(sqrtf(t), 1e-12f);
    }
    __syncthreads();

    // ---- phase 3: rand GEMM on tensor cores, hi+lo split dep ----
    {
        unsigned aHBase = (unsigned)__cvta_generic_to_shared(s_depH);
        unsigned aLBase = (unsigned)__cvta_generic_to_shared(s_depL);
        unsigned bBase  = (unsigned)__cvta_generic_to_shared(s_randH);
        const int pxb = (ty & 3) * 16;
        const int kb0 = (ty >> 2) * 16;
        const unsigned aRow = (unsigned)(pxb + (tx & 15)) * ROWQ + (unsigned)(tx >> 4);
        const unsigned bRow0 = (unsigned)(kb0 + (tx & 7)) * ROWQ + (unsigned)((tx >> 3) & 1);
        const unsigned bRow1 = bRow0 + 8u*ROWQ;
        float d0[4] = {0,0,0,0}, d1[4] = {0,0,0,0};
        #pragma unroll
        for (int kk = 0; kk < 16; kk++) {
            unsigned ah[4], al[4], b0r[2], b1r[2];
            ldmx4(ah,  aHBase + (aRow  + 2*kk) * 16);
            ldmx4(al,  aLBase + (aRow  + 2*kk) * 16);
            ldmx2(b0r, bBase  + (bRow0 + 2*kk) * 16);
            ldmx2(b1r, bBase  + (bRow1 + 2*kk) * 16);
            mma16816(d0, ah, b0r);
            mma16816(d0, al, b0r);
            mma16816(d1, ah, b1r);
            mma16816(d1, al, b1r);
        }
        int pxl = pxb + (tx >> 2);
        int kl  = (tx & 3) * 2;
        s_sim[(kb0 + kl + 0)*65 + pxl]     = d0[0];
        s_sim[(kb0 + kl + 1)*65 + pxl]     = d0[1];
        s_sim[(kb0 + kl + 0)*65 + pxl + 8] = d0[2];
        s_sim[(kb0 + kl + 1)*65 + pxl + 8] = d0[3];
        s_sim[(kb0 + 8 + kl + 0)*65 + pxl]     = d1[0];
        s_sim[(kb0 + 8 + kl + 1)*65 + pxl]     = d1[1];
        s_sim[(kb0 + 8 + kl + 0)*65 + pxl + 8] = d1[2];
        s_sim[(kb0 + 8 + kl + 1)*65 + pxl + 8] = d1[3];
    }

    // ---- phase 2: pos_sim (warp handles 8 pixels), dep = hi + lo ----
    const float* projU = proj + b*2*NN;
    const float* projV = projU + NN;
    const uint4* depHQ = reinterpret_cast<const uint4*>(s_depH);
    const uint4* depLQ = reinterpret_cast<const uint4*>(s_depL);
    #pragma unroll
    for (int q = 0; q < 8; q++) {
        int px = ty*8 + q;
        int n  = n0 + px;
        float pu = projU[n], pv = projV[n];
        float x0f = floorf(pu), y0f = floorf(pv);
        float wx = pu - x0f, wy = pv - y0f;
        int x0 = (int)x0f, y0 = (int)y0f;
        float w00 = (1.0f-wx)*(1.0f-wy), w10 = wx*(1.0f-wy);
        float w01 = (1.0f-wx)*wy,        w11 = wx*wy;
        int i00 = corner_idx(x0,   y0,   w00);
        int i10 = corner_idx(x0+1, y0,   w10);
        int i01 = corner_idx(x0,   y0+1, w01);
        int i11 = corner_idx(x0+1, y0+1, w11);
        const uint4* r00 = reinterpret_cast<const uint4*>(g_rgbTh + (size_t)(b*NN + i00)*CC);
        const uint4* r10 = reinterpret_cast<const uint4*>(g_rgbTh + (size_t)(b*NN + i10)*CC);
        const uint4* r01 = reinterpret_cast<const uint4*>(g_rgbTh + (size_t)(b*NN + i01)*CC);
        const uint4* r11 = reinterpret_cast<const uint4*>(g_rgbTh + (size_t)(b*NN + i11)*CC);
        uint4 dqh = depHQ[px*ROWQ + tx];
        uint4 dql = depLQ[px*ROWQ + tx];
        uint4 q00 = r00[tx], q10 = r10[tx], q01 = r01[tx], q11 = r11[tx];
        float pacc = 0.0f;
        const unsigned* duh = &dqh.x;
        const unsigned* dul = &dql.x;
        const unsigned* u00 = &q00.x;
        const unsigned* u10 = &q10.x;
        const unsigned* u01 = &q01.x;
        const unsigned* u11 = &q11.x;
        #pragma unroll
        for (int j = 0; j < 4; j++) {
            float2 dh = __half22float2(*reinterpret_cast<const __half2*>(&duh[j]));
            float2 dl = __half22float2(*reinterpret_cast<const __half2*>(&dul[j]));
            float dx = dh.x + dl.x, dy = dh.y + dl.y;
            float2 a00 = __half22float2(*reinterpret_cast<const __half2*>(&u00[j]));
            float2 a10 = __half22float2(*reinterpret_cast<const __half2*>(&u10[j]));
            float2 a01 = __half22float2(*reinterpret_cast<const __half2*>(&u01[j]));
            float2 a11 = __half22float2(*reinterpret_cast<const __half2*>(&u11[j]));
            pacc += dx*(w00*a00.x + w10*a10.x + w01*a01.x + w11*a11.x);
            pacc += dy*(w00*a00.y + w10*a10.y + w01*a01.y + w11*a11.y);
        }
        #pragma unroll
        for (int o = 16; o; o >>= 1) pacc += __shfl_xor_sync(0xffffffffu, pacc, o);
        if (tx == 0) s_pos[px] = pacc;
    }

    // ---- grid-point dep dump (hi+lo -> fp32, normalized * TEMP_INV) ----
    const int v_row = n0 >> 7;
    const int u0 = n0 & 127;
    const bool gridRow = ((v_row & 7) == 0);
    if (gridRow) {
        int px = ty*8;
        int p = ((v_row >> 3) << 4) + ((u0 + px) >> 3);
        float sc = s_inv[px] * TEMP_INV;
        float* dst = g_depGrid + (b*NPOS + p)*CC;
        uint4 dqh = depHQ[px*ROWQ + tx];
        uint4 dql = depLQ[px*ROWQ + tx];
        const unsigned* duh = &dqh.x;
        const unsigned* dul = &dql.x;
        float4 o0, o1;
        float2 fh, fl;
        fh = __half22float2(*reinterpret_cast<const __half2*>(&duh[0]));
        fl = __half22float2(*reinterpret_cast<const __half2*>(&dul[0]));
        o0.x = (fh.x+fl.x)*sc; o0.y = (fh.y+fl.y)*sc;
        fh = __half22float2(*reinterpret_cast<const __half2*>(&duh[1]));
        fl = __half22float2(*reinterpret_cast<const __half2*>(&dul[1]));
        o0.z = (fh.x+fl.x)*sc; o0.w = (fh.y+fl.y)*sc;
        fh = __half22float2(*reinterpret_cast<const __half2*>(&duh[2]));
        fl = __half22float2(*reinterpret_cast<const __half2*>(&dul[2]));
        o1.x = (fh.x+fl.x)*sc; o1.y = (fh.y+fl.y)*sc;
        fh = __half22float2(*reinterpret_cast<const __half2*>(&duh[3]));
        fl = __half22float2(*reinterpret_cast<const __half2*>(&dul[3]));
        o1.z = (fh.x+fl.x)*sc; o1.w = (fh.y+fl.y)*sc;
        reinterpret_cast<float4*>(dst + tx*8)[0] = o0;
        reinterpret_cast<float4*>(dst + tx*8)[1] = o1;
    }
    __syncthreads();

    // ---- phase 4: logsumexp / max + fused loss for non-grid pixels ----
    float wl = 0.0f, wm = 0.0f, wc = 0.0f;
    #pragma unroll
    for (int q = 0; q < 8; q++) {
        int px = ty*8 + q;
        float scale = s_inv[px] * TEMP_INV;
        float pos = s_pos[px] * scale;
        float v = s_sim[tx*65 + px] * scale;
        float mneg = v;
        #pragma unroll
        for (int o = 16; o; o >>= 1) mneg = fmaxf(mneg, __shfl_xor_sync(0xffffffffu, mneg, o));
        float m = fmaxf(pos, mneg);
        float e = expf(v - m);
        #pragma unroll
        for (int o = 16; o; o >>= 1) e += __shfl_xor_sync(0xffffffffu, e, o);
        if (tx == 0) {
            float lse = m + logf(e + expf(pos - m));
            bool isGrid = gridRow && (q == 0);
            if (isGrid) {
                int p = ((v_row >> 3) << 4) + ((u0 + px) >> 3);
                g_posG[b*NPOS + p] = pos;
                g_lseG[b*NPOS + p] = lse;
                g_mxG [b*NPOS + p] = mneg;
            } else {
                float mask = valid[b*NN + n0 + px];
                wl += (lse - pos) * mask;
                wm += mask;
                wc += (pos > mneg && mask > 0.5f) ? 1.0f : 0.0f;
            }
        }
    }
    __syncthreads();
    if (tx == 0) {
        s_red[ty] = wl;
        s_red[8 + ty] = wm;
        s_red[16 + ty] = wc;
    }
    __syncthreads();
    if (tid == 0) {
        float a = 0.f, b2 = 0.f, c2 = 0.f;
        #pragma unroll
        for (int j = 0; j < 8; j++) { a += s_red[j]; b2 += s_red[8+j]; c2 += s_red[16+j]; }
        atomicAdd(&g_acc[0], a);
        atomicAdd(&g_acc[1], b2);
        atomicAdd(&g_acc[2], c2);
    }
}

// ---------------- kernel 3: hard negatives + grid-pixel loss + epilogue ------
__global__ __launch_bounds__(256) void k_hard(const float* __restrict__ proj,
                                              const int*   __restrict__ offu,
                                              const int*   __restrict__ offv,
                                              const float* __restrict__ valid,
                                              float* __restrict__ out) {
    __shared__ float s_depv[CC];
    __shared__ float s_hsim[NHARD];
    const int tid = threadIdx.x;
    const int tx = tid & 31;
    const int ty = tid >> 5;
    const int b = blockIdx.x >> 8;
    const int p = blockIdx.x & 255;
    const int gh = (p >> 4) * 8;
    const int gw = (p & 15) * 8;
    const int ng = gh*WW + gw;

    s_depv[tid] = g_depGrid[(b*NPOS + p)*CC + tid];
    __syncthreads();

    float pu = proj[b*2*NN + ng];
    float pv = proj[b*2*NN + NN + ng];
    int posu = (int)fminf(fmaxf(pu, 0.0f), (float)(WW-1));
    int posv = (int)fminf(fmaxf(pv, 0.0f), (float)(HH-1));

    const uint4* r[12];
    #pragma unroll
    for (int j = 0; j < 12; j++) {
        int h = ty*12 + j;
        int ou = offu[(b*NHARD + h)*NPOS + p];
        int ov = offv[(b*NHARD + h)*NPOS + p];
        if (ou == 0 && ov == 0) ou = 1;
        int hu = min(max(posu + ou, 0), WW-1);
        int hv = min(max(posv + ov, 0), HH-1);
        r[j] = reinterpret_cast<const uint4*>(g_rgbTh + (size_t)(b*NN + hv*WW + hu)*CC);
    }
    uint4 q[12];
    #pragma unroll
    for (int j = 0; j < 12; j++) q[j] = r[j][tx];

    const float4* dv = reinterpret_cast<const float4*>(s_depv);
    float4 d0 = dv[2*tx];
    float4 d1 = dv[2*tx + 1];
    float acc[12];
    #pragma unroll
    for (int j = 0; j < 12; j++) {
        float2 f0 = __half22float2(*reinterpret_cast<__half2*>(&q[j].x));
        float2 f1 = __half22float2(*reinterpret_cast<__half2*>(&q[j].y));
        float2 f2 = __half22float2(*reinterpret_cast<__half2*>(&q[j].z));
        float2 f3 = __half22float2(*reinterpret_cast<__half2*>(&q[j].w));
        float a = 0.0f;
        a += d0.x*f0.x; a += d0.y*f0.y; a += d0.z*f1.x; a += d0.w*f1.y;
        a += d1.x*f2.x; a += d1.y*f2.y; a += d1.z*f3.x; a += d1.w*f3.y;
        acc[j] = a;
    }
    #pragma unroll
    for (int o = 16; o; o >>= 1) {
        #pragma unroll
        for (int j = 0; j < 12; j++)
            acc[j] += __shfl_xor_sync(0xffffffffu, acc[j], o);
    }
    if (tx == 0) {
        #pragma unroll
        for (int j = 0; j < 12; j++) s_hsim[ty*12 + j] = acc[j];
    }
    __syncthreads();

    if (tid < 32) {
        float v0 = s_hsim[tx];
        float v1 = s_hsim[tx + 32];
        float v2 = s_hsim[tx + 64];
        float m = fmaxf(fmaxf(v0, v1), v2);
        #pragma unroll
        for (int o = 16; o; o >>= 1) m = fmaxf(m, __shfl_xor_sync(0xffffffffu, m, o));
        float se = expf(v0 - m) + expf(v1 - m) + expf(v2 - m);
        #pragma unroll
        for (int o = 16; o; o >>= 1) se += __shfl_xor_sync(0xffffffffu, se, o);
        if (tx == 0) {
            float lse_h = m + logf(se);
            int bp = b*NPOS + p;
            float pos = g_posG[bp];
            float lse0 = g_lseG[bp];
            float mx0 = g_mxG[bp];
            float mm = fmaxf(lse0, lse_h);
            float lse = mm + logf(expf(lse0 - mm) + expf(lse_h - mm));
            float mx = fmaxf(mx0, m);
            float mask = valid[b*NN + ng];
            float lossp = (lse - pos) * mask;
            float corr = (pos > mx && mask > 0.5f) ? 1.0f : 0.0f;
            atomicAdd(&g_acc[0], lossp);
            atomicAdd(&g_acc[1], mask);
            atomicAdd(&g_acc[2], corr);
            __threadfence();
            unsigned t = atomicAdd(&g_done, 1u);
            if (t == (unsigned)(BB*NPOS) - 1u) {
                __threadfence();
                float denom = fmaxf(g_acc[1], 1.0f);
                out[0] = g_acc[0] / denom;
                out[1] = g_acc[2] / denom * 100.0f;
            }
        }
    }
}

// ---------------- launch -------------------------------------------------------
extern "C" void kernel_launch(void* const* d_in, const int* in_sizes, int n_in,
                              void* d_out, int out_size) {
    const float* rgb   = (const float*)d_in[0];
    const float* dep   = (const float*)d_in[1];
    const float* proj  = (const float*)d_in[2];
    const float* valid = (const float*)d_in[3];
    const int*   ridx  = (const int*)d_in[4];
    const int*   offu  = (const int*)d_in[5];
    const int*   offv  = (const int*)d_in[6];
    float* out = (float*)d_out;

    const int smem_norm = (CC*TSTR + 8*TSTR + 32) * (int)sizeof(float) + 32*ROWQ*16;
    cudaFuncSetAttribute(k_norm_t, cudaFuncAttributeMaxDynamicSharedMemorySize, smem_norm);

    const int smem_main = 64*ROWQ*16*2 + 32*ROWQ*16
                        + (NRAND*65 + 64 + 64 + 4*65) * (int)sizeof(float);
    cudaFuncSetAttribute(k_main, cudaFuncAttributeMaxDynamicSharedMemorySize, smem_main);

    k_norm_t<<<BB*NN/32, 256, smem_norm>>>(rgb);
    k_main<<<BB*NN/64, 256, smem_main>>>(dep, proj, ridx, valid);
    k_hard<<<BB*NPOS, 256>>>(proj, offu, offv, valid, out);
}

// round 13
// speedup vs baseline: 1.4425x; 1.0765x over previous
#include <cuda_runtime.h>
#include <cuda_fp16.h>
#include <math.h>

#define BB 8
#define CC 256
#define HH 128
#define WW 128
#define NN (HH*WW)          // 16384
#define NPOS 256
#define NHARD 96
#define NRAND 32
#define TEMP_INV (1.0f/0.07f)

#define ROWQ 33             // quads (16B units) per padded fp16 row (264 halves)
#define TSTR 36             // fp32 tile row stride (floats), float4-aligned

// ---------------- scratch (static device globals; no allocation) ------------
__device__ __half g_rgbTh[BB*NN*CC];    // normalized rgb (fp16), [b][px][ch]
__device__ float g_depGrid[BB*NPOS*CC]; // normalized*TEMP_INV dep at grid pts
__device__ float g_posG[BB*NPOS];       // pos_sim at grid points
__device__ float g_lseG[BB*NPOS];       // base lse at grid points
__device__ float g_mxG[BB*NPOS];        // rand max at grid points
__device__ float g_acc[3];              // loss_sum, mask_sum, correct_sum
__device__ unsigned g_done;

// ---------------- mma/ldmatrix helpers ---------------------------------------
__device__ __forceinline__ void ldmx4(unsigned* r, unsigned addr) {
    asm volatile("ldmatrix.sync.aligned.m8n8.x4.shared.b16 {%0,%1,%2,%3}, [%4];"
                 : "=r"(r[0]), "=r"(r[1]), "=r"(r[2]), "=r"(r[3]) : "r"(addr));
}
__device__ __forceinline__ void ldmx2(unsigned* r, unsigned addr) {
    asm volatile("ldmatrix.sync.aligned.m8n8.x2.shared.b16 {%0,%1}, [%2];"
                 : "=r"(r[0]), "=r"(r[1]) : "r"(addr));
}
__device__ __forceinline__ void mma16816(float* d, const unsigned* a, const unsigned* b) {
    asm volatile(
        "mma.sync.aligned.m16n8k16.row.col.f32.f16.f16.f32 "
        "{%0,%1,%2,%3}, {%4,%5,%6,%7}, {%8,%9}, {%0,%1,%2,%3};"
        : "+f"(d[0]), "+f"(d[1]), "+f"(d[2]), "+f"(d[3])
        : "r"(a[0]), "r"(a[1]), "r"(a[2]), "r"(a[3]),
          "r"(b[0]), "r"(b[1]));
}

// ---------------- kernel 1: normalize + transpose (float4 loads) -------------
__global__ __launch_bounds__(256) void k_norm_t(const float* __restrict__ in) {
    extern __shared__ float smn[];
    float*  s_tile = smn;                         // CC * 36 floats
    float*  s_red  = s_tile + CC*TSTR;            // 8 * 36
    float*  s_inv  = s_red + 8*TSTR;              // 32
    __half* s_half = reinterpret_cast<__half*>(s_inv + 32);   // 32 * 264 halves

    const int tid = threadIdx.x;
    const int tx = tid & 31;
    const int ty = tid >> 5;
    const int blocksPerBatch = NN/32;
    const int b  = blockIdx.x / blocksPerBatch;
    const int n0 = (blockIdx.x % blocksPerBatch) * 32;

    if (blockIdx.x == 0 && tid < 3) g_acc[tid] = 0.0f;
    if (blockIdx.x == 0 && tid == 3) g_done = 0;

    const float* src = in + b*CC*NN + n0;
    const int pxg = tid & 7;
    const int c0  = tid >> 3;
    float ss0 = 0.f, ss1 = 0.f, ss2 = 0.f, ss3 = 0.f;
    #pragma unroll
    for (int pass = 0; pass < 8; pass++) {
        int c = pass*32 + c0;
        float4 v = *reinterpret_cast<const float4*>(src + c*NN + pxg*4);
        *reinterpret_cast<float4*>(&s_tile[c*TSTR + pxg*4]) = v;
        ss0 += v.x*v.x; ss1 += v.y*v.y; ss2 += v.z*v.z; ss3 += v.w*v.w;
    }
    #pragma unroll
    for (int o = 8; o <= 16; o <<= 1) {
        ss0 += __shfl_xor_sync(0xffffffffu, ss0, o);
        ss1 += __shfl_xor_sync(0xffffffffu, ss1, o);
        ss2 += __shfl_xor_sync(0xffffffffu, ss2, o);
        ss3 += __shfl_xor_sync(0xffffffffu, ss3, o);
    }
    if (tx < 8) {
        *reinterpret_cast<float4*>(&s_red[ty*TSTR + tx*4]) =
            make_float4(ss0, ss1, ss2, ss3);
    }
    __syncthreads();
    if (tid < 32) {
        float t = 0.0f;
        #pragma unroll
        for (int w = 0; w < 8; w++) t += s_red[w*TSTR + tid];
        s_inv[tid] = 1.0f / fmaxf(sqrtf(t), 1e-12f);
    }
    __syncthreads();

    {
        const int px = tx;
        float inv = s_inv[px];
        uint4* hrow = reinterpret_cast<uint4*>(s_half) + px*ROWQ;
        #pragma unroll
        for (int cc2 = 0; cc2 < 4; cc2++) {
            int ch = ty*4 + cc2;
            float v[8];
            #pragma unroll
            for (int j = 0; j < 8; j++) v[j] = s_tile[(ch*8 + j)*TSTR + px] * inv;
            uint4 q;
            __half2 h;
            h = __floats2half2_rn(v[0], v[1]); q.x = *reinterpret_cast<unsigned*>(&h);
            h = __floats2half2_rn(v[2], v[3]); q.y = *reinterpret_cast<unsigned*>(&h);
            h = __floats2half2_rn(v[4], v[5]); q.z = *reinterpret_cast<unsigned*>(&h);
            h = __floats2half2_rn(v[6], v[7]); q.w = *reinterpret_cast<unsigned*>(&h);
            hrow[ch] = q;
        }
    }
    __syncthreads();

    {
        uint4* dst = reinterpret_cast<uint4*>(g_rgbTh + (size_t)(b*NN + n0)*CC);
        const uint4* srcq = reinterpret_cast<const uint4*>(s_half);
        const int cb = tid & 31;
        const int pq = tid >> 5;
        #pragma unroll
        for (int it = 0; it < 4; it++) {
            int px = it*8 + pq;
            dst[px*(CC/8) + cb] = srcq[px*ROWQ + cb];
        }
    }
}

// ---------------- kernel 2: main pass (32 px tiles, 4 blocks/SM) -------------
__device__ __forceinline__ int corner_idx(int xx, int yy, float& w) {
    bool v = (xx >= 0) & (xx < WW) & (yy >= 0) & (yy < HH);
    if (!v) w = 0.0f;
    int cx = min(max(xx, 0), WW-1);
    int cy = min(max(yy, 0), HH-1);
    return cy*WW + cx;
}

__global__ __launch_bounds__(256) void k_main(const float* __restrict__ dep,
                                              const float* __restrict__ proj,
                                              const int*   __restrict__ rand_idx,
                                              const float* __restrict__ valid) {
    extern __shared__ float sm[];
    __half* s_depH  = reinterpret_cast<__half*>(sm);     // hi: 32*264 halves
    __half* s_depL  = s_depH + 32*ROWQ*8;                // lo: 32*264 halves
    __half* s_randH = s_depL + 32*ROWQ*8;                // 32*264 halves
    float*  s_sim   = reinterpret_cast<float*>(s_randH + 32*ROWQ*8); // 32*33
    float*  s_pos   = s_sim + NRAND*33;                  // 32
    float*  s_inv   = s_pos + 32;                        // 32
    float*  s_red   = s_inv + 32;                        // 8*33

    const int tid = threadIdx.x;
    const int tx  = tid & 31;
    const int ty  = tid >> 5;                  // warp id 0..7
    const int b  = blockIdx.x >> 9;            // 512 blocks per batch
    const int n0 = (blockIdx.x & 511) * 32;

    // ---- stage dep tile split fp16 hi/lo + partial norms (fp32) ----
    {
        const int px = tx;
        const int cg = ty;                     // chunks cg*4..cg*4+3
        const float* dsrc = dep + b*CC*NN + n0 + px;
        float ss = 0.0f;
        uint4* hrow = reinterpret_cast<uint4*>(s_depH) + px*ROWQ;
        uint4* lrow = reinterpret_cast<uint4*>(s_depL) + px*ROWQ;
        #pragma unroll
        for (int j = 0; j < 4; j++) {
            int chunk = cg*4 + j;
            float v[8];
            __half hi[8], lo[8];
            #pragma unroll
            for (int t = 0; t < 8; t++) {
                v[t] = dsrc[(chunk*8 + t)*NN];
                ss += v[t]*v[t];
                hi[t] = __float2half_rn(v[t]);
                lo[t] = __float2half_rn(v[t] - __half2float(hi[t]));
            }
            uint4 qh, ql;
            __half2 h;
            h = __halves2half2(hi[0], hi[1]); qh.x = *reinterpret_cast<unsigned*>(&h);
            h = __halves2half2(hi[2], hi[3]); qh.y = *reinterpret_cast<unsigned*>(&h);
            h = __halves2half2(hi[4], hi[5]); qh.z = *reinterpret_cast<unsigned*>(&h);
            h = __halves2half2(hi[6], hi[7]); qh.w = *reinterpret_cast<unsigned*>(&h);
            h = __halves2half2(lo[0], lo[1]); ql.x = *reinterpret_cast<unsigned*>(&h);
            h = __halves2half2(lo[2], lo[3]); ql.y = *reinterpret_cast<unsigned*>(&h);
            h = __halves2half2(lo[4], lo[5]); ql.z = *reinterpret_cast<unsigned*>(&h);
            h = __halves2half2(lo[6], lo[7]); ql.w = *reinterpret_cast<unsigned*>(&h);
            hrow[chunk] = qh;
            lrow[chunk] = ql;
        }
        s_red[cg*33 + px] = ss;
    }
    // ---- stage rand vectors (fp16 rows, padded) ----
    {
        int k = tid >> 3, part = tid & 7;
        int ridx = rand_idx[b*NRAND + k];
        const uint4* row = reinterpret_cast<const uint4*>(g_rgbTh + (size_t)(b*NN + ridx)*CC);
        uint4* drow = reinterpret_cast<uint4*>(s_randH) + k*ROWQ;
        #pragma unroll
        for (int i = 0; i < 4; i++) {
            int chunk = part + 8*i;
            drow[chunk] = row[chunk];
        }
    }
    __syncthreads();
    if (tid < 32) {
        float t = 0.0f;
        #pragma unroll
        for (int w = 0; w < 8; w++) t += s_red[w*33 + tid];
        s_inv[tid] = 1.0f / fmaxf(sqrtf(t), 1e-12f);
    }
    __syncthreads();

    // ---- phase 3: rand GEMM on tensor cores, hi+lo, K split across warps ----
    {
        unsigned aHBase = (unsigned)__cvta_generic_to_shared(s_depH);
        unsigned aLBase = (unsigned)__cvta_generic_to_shared(s_depL);
        unsigned bBase  = (unsigned)__cvta_generic_to_shared(s_randH);
        const int pxb = (ty & 1) * 16;
        const int kb0 = ((ty >> 1) & 1) * 16;
        const int kh  = ty >> 2;               // K-half 0/1
        const unsigned aRow = (unsigned)(pxb + (tx & 15)) * ROWQ + (unsigned)(tx >> 4);
        const unsigned bRow0 = (unsigned)(kb0 + (tx & 7)) * ROWQ + (unsigned)((tx >> 3) & 1);
        const unsigned bRow1 = bRow0 + 8u*ROWQ;
        float d0[4] = {0,0,0,0}, d1[4] = {0,0,0,0};
        #pragma unroll
        for (int kk = 0; kk < 8; kk++) {
            int ck = kh*8 + kk;
            unsigned ah[4], al[4], b0r[2], b1r[2];
            ldmx4(ah,  aHBase + (aRow  + 2*ck) * 16);
            ldmx4(al,  aLBase + (aRow  + 2*ck) * 16);
            ldmx2(b0r, bBase  + (bRow0 + 2*ck) * 16);
            ldmx2(b1r, bBase  + (bRow1 + 2*ck) * 16);
            mma16816(d0, ah, b0r);
            mma16816(d0, al, b0r);
            mma16816(d1, ah, b1r);
            mma16816(d1, al, b1r);
        }
        int pxl = pxb + (tx >> 2);
        int kl  = (tx & 3) * 2;
        if (kh == 0) {
            s_sim[(kb0 + kl + 0)*33 + pxl]     = d0[0];
            s_sim[(kb0 + kl + 1)*33 + pxl]     = d0[1];
            s_sim[(kb0 + kl + 0)*33 + pxl + 8] = d0[2];
            s_sim[(kb0 + kl + 1)*33 + pxl + 8] = d0[3];
            s_sim[(kb0 + 8 + kl + 0)*33 + pxl]     = d1[0];
            s_sim[(kb0 + 8 + kl + 1)*33 + pxl]     = d1[1];
            s_sim[(kb0 + 8 + kl + 0)*33 + pxl + 8] = d1[2];
            s_sim[(kb0 + 8 + kl + 1)*33 + pxl + 8] = d1[3];
        }
        __syncthreads();
        if (kh == 1) {
            s_sim[(kb0 + kl + 0)*33 + pxl]     += d0[0];
            s_sim[(kb0 + kl + 1)*33 + pxl]     += d0[1];
            s_sim[(kb0 + kl + 0)*33 + pxl + 8] += d0[2];
            s_sim[(kb0 + kl + 1)*33 + pxl + 8] += d0[3];
            s_sim[(kb0 + 8 + kl + 0)*33 + pxl]     += d1[0];
            s_sim[(kb0 + 8 + kl + 1)*33 + pxl]     += d1[1];
            s_sim[(kb0 + 8 + kl + 0)*33 + pxl + 8] += d1[2];
            s_sim[(kb0 + 8 + kl + 1)*33 + pxl + 8] += d1[3];
        }
    }

    // ---- phase 2: pos_sim (warp handles 4 pixels), dep = hi + lo ----
    const float* projU = proj + b*2*NN;
    const float* projV = projU + NN;
    const uint4* depHQ = reinterpret_cast<const uint4*>(s_depH);
    const uint4* depLQ = reinterpret_cast<const uint4*>(s_depL);
    #pragma unroll
    for (int q = 0; q < 4; q++) {
        int px = ty*4 + q;
        int n  = n0 + px;
        float pu = projU[n], pv = projV[n];
        float x0f = floorf(pu), y0f = floorf(pv);
        float wx = pu - x0f, wy = pv - y0f;
        int x0 = (int)x0f, y0 = (int)y0f;
        float w00 = (1.0f-wx)*(1.0f-wy), w10 = wx*(1.0f-wy);
        float w01 = (1.0f-wx)*wy,        w11 = wx*wy;
        int i00 = corner_idx(x0,   y0,   w00);
        int i10 = corner_idx(x0+1, y0,   w10);
        int i01 = corner_idx(x0,   y0+1, w01);
        int i11 = corner_idx(x0+1, y0+1, w11);
        const uint4* r00 = reinterpret_cast<const uint4*>(g_rgbTh + (size_t)(b*NN + i00)*CC);
        const uint4* r10 = reinterpret_cast<const uint4*>(g_rgbTh + (size_t)(b*NN + i10)*CC);
        const uint4* r01 = reinterpret_cast<const uint4*>(g_rgbTh + (size_t)(b*NN + i01)*CC);
        const uint4* r11 = reinterpret_cast<const uint4*>(g_rgbTh + (size_t)(b*NN + i11)*CC);
        uint4 dqh = depHQ[px*ROWQ + tx];
        uint4 dql = depLQ[px*ROWQ + tx];
        uint4 q00 = r00[tx], q10 = r10[tx], q01 = r01[tx], q11 = r11[tx];
        float pacc = 0.0f;
        const unsigned* duh = &dqh.x;
        const unsigned* dul = &dql.x;
        const unsigned* u00 = &q00.x;
        const unsigned* u10 = &q10.x;
        const unsigned* u01 = &q01.x;
        const unsigned* u11 = &q11.x;
        #pragma unroll
        for (int j = 0; j < 4; j++) {
            float2 dh = __half22float2(*reinterpret_cast<const __half2*>(&duh[j]));
            float2 dl = __half22float2(*reinterpret_cast<const __half2*>(&dul[j]));
            float dx = dh.x + dl.x, dy = dh.y + dl.y;
            float2 a00 = __half22float2(*reinterpret_cast<const __half2*>(&u00[j]));
            float2 a10 = __half22float2(*reinterpret_cast<const __half2*>(&u10[j]));
            float2 a01 = __half22float2(*reinterpret_cast<const __half2*>(&u01[j]));
            float2 a11 = __half22float2(*reinterpret_cast<const __half2*>(&u11[j]));
            pacc += dx*(w00*a00.x + w10*a10.x + w01*a01.x + w11*a11.x);
            pacc += dy*(w00*a00.y + w10*a10.y + w01*a01.y + w11*a11.y);
        }
        #pragma unroll
        for (int o = 16; o; o >>= 1) pacc += __shfl_xor_sync(0xffffffffu, pacc, o);
        if (tx == 0) s_pos[px] = pacc;
    }

    // ---- grid-point dep dump (hi+lo -> fp32, normalized * TEMP_INV) ----
    const int v_row = n0 >> 7;
    const int u0 = n0 & 127;
    const bool gridRow = ((v_row & 7) == 0);
    if (gridRow && ty < 4) {
        int px = ty*8;     // grid pixels 0,8,16,24
        int p = ((v_row >> 3) << 4) + ((u0 + px) >> 3);
        float sc = s_inv[px] * TEMP_INV;
        float* dst = g_depGrid + (b*NPOS + p)*CC;
        uint4 dqh = depHQ[px*ROWQ + tx];
        uint4 dql = depLQ[px*ROWQ + tx];
        const unsigned* duh = &dqh.x;
        const unsigned* dul = &dql.x;
        float4 o0, o1;
        float2 fh, fl;
        fh = __half22float2(*reinterpret_cast<const __half2*>(&duh[0]));
        fl = __half22float2(*reinterpret_cast<const __half2*>(&dul[0]));
        o0.x = (fh.x+fl.x)*sc; o0.y = (fh.y+fl.y)*sc;
        fh = __half22float2(*reinterpret_cast<const __half2*>(&duh[1]));
        fl = __half22float2(*reinterpret_cast<const __half2*>(&dul[1]));
        o0.z = (fh.x+fl.x)*sc; o0.w = (fh.y+fl.y)*sc;
        fh = __half22float2(*reinterpret_cast<const __half2*>(&duh[2]));
        fl = __half22float2(*reinterpret_cast<const __half2*>(&dul[2]));
        o1.x = (fh.x+fl.x)*sc; o1.y = (fh.y+fl.y)*sc;
        fh = __half22float2(*reinterpret_cast<const __half2*>(&duh[3]));
        fl = __half22float2(*reinterpret_cast<const __half2*>(&dul[3]));
        o1.z = (fh.x+fl.x)*sc; o1.w = (fh.y+fl.y)*sc;
        reinterpret_cast<float4*>(dst + tx*8)[0] = o0;
        reinterpret_cast<float4*>(dst + tx*8)[1] = o1;
    }
    __syncthreads();

    // ---- phase 4: logsumexp / max + fused loss for non-grid pixels ----
    float wl = 0.0f, wm = 0.0f, wc = 0.0f;
    #pragma unroll
    for (int q = 0; q < 4; q++) {
        int px = ty*4 + q;
        float scale = s_inv[px] * TEMP_INV;
        float pos = s_pos[px] * scale;
        float v = s_sim[tx*33 + px] * scale;
        float mneg = v;
        #pragma unroll
        for (int o = 16; o; o >>= 1) mneg = fmaxf(mneg, __shfl_xor_sync(0xffffffffu, mneg, o));
        float m = fmaxf(pos, mneg);
        float e = expf(v - m);
        #pragma unroll
        for (int o = 16; o; o >>= 1) e += __shfl_xor_sync(0xffffffffu, e, o);
        if (tx == 0) {
            float lse = m + logf(e + expf(pos - m));
            bool isGrid = gridRow && (q == 0) && ((ty & 1) == 0);  // px%8==0
            if (isGrid) {
                int p = ((v_row >> 3) << 4) + ((u0 + px) >> 3);
                g_posG[b*NPOS + p] = pos;
                g_lseG[b*NPOS + p] = lse;
                g_mxG [b*NPOS + p] = mneg;
            } else {
                float mask = valid[b*NN + n0 + px];
                wl += (lse - pos) * mask;
                wm += mask;
                wc += (pos > mneg && mask > 0.5f) ? 1.0f : 0.0f;
            }
        }
    }
    __syncthreads();
    if (tx == 0) {
        s_red[ty] = wl;
        s_red[8 + ty] = wm;
        s_red[16 + ty] = wc;
    }
    __syncthreads();
    if (tid == 0) {
        float a = 0.f, b2 = 0.f, c2 = 0.f;
        #pragma unroll
        for (int j = 0; j < 8; j++) { a += s_red[j]; b2 += s_red[8+j]; c2 += s_red[16+j]; }
        atomicAdd(&g_acc[0], a);
        atomicAdd(&g_acc[1], b2);
        atomicAdd(&g_acc[2], c2);
    }
}

// ---------------- kernel 3: hard negatives + grid-pixel loss + epilogue ------
__global__ __launch_bounds__(256) void k_hard(const float* __restrict__ proj,
                                              const int*   __restrict__ offu,
                                              const int*   __restrict__ offv,
                                              const float* __restrict__ valid,
                                              float* __restrict__ out) {
    __shared__ float s_depv[CC];
    __shared__ float s_hsim[NHARD];
    const int tid = threadIdx.x;
    const int tx = tid & 31;
    const int ty = tid >> 5;
    const int b = blockIdx.x >> 8;
    const int p = blockIdx.x & 255;
    const int gh = (p >> 4) * 8;
    const int gw = (p & 15) * 8;
    const int ng = gh*WW + gw;

    s_depv[tid] = g_depGrid[(b*NPOS + p)*CC + tid];
    __syncthreads();

    float pu = proj[b*2*NN + ng];
    float pv = proj[b*2*NN + NN + ng];
    int posu = (int)fminf(fmaxf(pu, 0.0f), (float)(WW-1));
    int posv = (int)fminf(fmaxf(pv, 0.0f), (float)(HH-1));

    const uint4* r[12];
    #pragma unroll
    for (int j = 0; j < 12; j++) {
        int h = ty*12 + j;
        int ou = offu[(b*NHARD + h)*NPOS + p];
        int ov = offv[(b*NHARD + h)*NPOS + p];
        if (ou == 0 && ov == 0) ou = 1;
        int hu = min(max(posu + ou, 0), WW-1);
        int hv = min(max(posv + ov, 0), HH-1);
        r[j] = reinterpret_cast<const uint4*>(g_rgbTh + (size_t)(b*NN + hv*WW + hu)*CC);
    }
    uint4 q[12];
    #pragma unroll
    for (int j = 0; j < 12; j++) q[j] = r[j][tx];

    const float4* dv = reinterpret_cast<const float4*>(s_depv);
    float4 d0 = dv[2*tx];
    float4 d1 = dv[2*tx + 1];
    float acc[12];
    #pragma unroll
    for (int j = 0; j < 12; j++) {
        float2 f0 = __half22float2(*reinterpret_cast<__half2*>(&q[j].x));
        float2 f1 = __half22float2(*reinterpret_cast<__half2*>(&q[j].y));
        float2 f2 = __half22float2(*reinterpret_cast<__half2*>(&q[j].z));
        float2 f3 = __half22float2(*reinterpret_cast<__half2*>(&q[j].w));
        float a = 0.0f;
        a += d0.x*f0.x; a += d0.y*f0.y; a += d0.z*f1.x; a += d0.w*f1.y;
        a += d1.x*f2.x; a += d1.y*f2.y; a += d1.z*f3.x; a += d1.w*f3.y;
        acc[j] = a;
    }
    #pragma unroll
    for (int o = 16; o; o >>= 1) {
        #pragma unroll
        for (int j = 0; j < 12; j++)
            acc[j] += __shfl_xor_sync(0xffffffffu, acc[j], o);
    }
    if (tx == 0) {
        #pragma unroll
        for (int j = 0; j < 12; j++) s_hsim[ty*12 + j] = acc[j];
    }
    __syncthreads();

    if (tid < 32) {
        float v0 = s_hsim[tx];
        float v1 = s_hsim[tx + 32];
        float v2 = s_hsim[tx + 64];
        float m = fmaxf(fmaxf(v0, v1), v2);
        #pragma unroll
        for (int o = 16; o; o >>= 1) m = fmaxf(m, __shfl_xor_sync(0xffffffffu, m, o));
        float se = expf(v0 - m) + expf(v1 - m) + expf(v2 - m);
        #pragma unroll
        for (int o = 16; o; o >>= 1) se += __shfl_xor_sync(0xffffffffu, se, o);
        if (tx == 0) {
            float lse_h = m + logf(se);
            int bp = b*NPOS + p;
            float pos = g_posG[bp];
            float lse0 = g_lseG[bp];
            float mx0 = g_mxG[bp];
            float mm = fmaxf(lse0, lse_h);
            float lse = mm + logf(expf(lse0 - mm) + expf(lse_h - mm));
            float mx = fmaxf(mx0, m);
            float mask = valid[b*NN + ng];
            float lossp = (lse - pos) * mask;
            float corr = (pos > mx && mask > 0.5f) ? 1.0f : 0.0f;
            atomicAdd(&g_acc[0], lossp);
            atomicAdd(&g_acc[1], mask);
            atomicAdd(&g_acc[2], corr);
            __threadfence();
            unsigned t = atomicAdd(&g_done, 1u);
            if (t == (unsigned)(BB*NPOS) - 1u) {
                __threadfence();
                float denom = fmaxf(g_acc[1], 1.0f);
                out[0] = g_acc[0] / denom;
                out[1] = g_acc[2] / denom * 100.0f;
            }
        }
    }
}

// ---------------- launch -------------------------------------------------------
extern "C" void kernel_launch(void* const* d_in, const int* in_sizes, int n_in,
                              void* d_out, int out_size) {
    const float* rgb   = (const float*)d_in[0];
    const float* dep   = (const float*)d_in[1];
    const float* proj  = (const float*)d_in[2];
    const float* valid = (const float*)d_in[3];
    const int*   ridx  = (const int*)d_in[4];
    const int*   offu  = (const int*)d_in[5];
    const int*   offv  = (const int*)d_in[6];
    float* out = (float*)d_out;

    const int smem_norm = (CC*TSTR + 8*TSTR + 32) * (int)sizeof(float) + 32*ROWQ*16;
    cudaFuncSetAttribute(k_norm_t, cudaFuncAttributeMaxDynamicSharedMemorySize, smem_norm);

    const int smem_main = 32*ROWQ*16*3
                        + (NRAND*33 + 32 + 32 + 8*33) * (int)sizeof(float);
    cudaFuncSetAttribute(k_main, cudaFuncAttributeMaxDynamicSharedMemorySize, smem_main);

    k_norm_t<<<BB*NN/32, 256, smem_norm>>>(rgb);
    k_main<<<BB*NN/32, 256, smem_main>>>(dep, proj, ridx, valid);
    k_hard<<<BB*NPOS, 256>>>(proj, offu, offv, valid, out);
}

// round 14
// speedup vs baseline: 1.4902x; 1.0331x over previous
#include <cuda_runtime.h>
#include <cuda_fp16.h>
#include <math.h>

#define BB 8
#define CC 256
#define HH 128
#define WW 128
#define NN (HH*WW)          // 16384
#define NPOS 256
#define NHARD 96
#define NRAND 32
#define TEMP_INV (1.0f/0.07f)

#define ROWQ 33             // quads (16B units) per padded fp16 row (264 halves)
#define TSTR 36             // fp32 tile row stride (floats), float4-aligned

// ---------------- scratch (static device globals; no allocation) ------------
__device__ __half g_rgbTh[BB*NN*CC];    // normalized rgb (fp16), [b][px][ch]
__device__ float g_depGrid[BB*NPOS*CC]; // normalized*TEMP_INV dep at grid pts
__device__ float g_posG[BB*NPOS];       // pos_sim at grid points
__device__ float g_lseG[BB*NPOS];       // base lse at grid points
__device__ float g_mxG[BB*NPOS];        // rand max at grid points
__device__ float g_acc[3];              // loss_sum, mask_sum, correct_sum
__device__ unsigned g_done;

// ---------------- mma/ldmatrix helpers ---------------------------------------
__device__ __forceinline__ void ldmx4(unsigned* r, unsigned addr) {
    asm volatile("ldmatrix.sync.aligned.m8n8.x4.shared.b16 {%0,%1,%2,%3}, [%4];"
                 : "=r"(r[0]), "=r"(r[1]), "=r"(r[2]), "=r"(r[3]) : "r"(addr));
}
__device__ __forceinline__ void ldmx2(unsigned* r, unsigned addr) {
    asm volatile("ldmatrix.sync.aligned.m8n8.x2.shared.b16 {%0,%1}, [%2];"
                 : "=r"(r[0]), "=r"(r[1]) : "r"(addr));
}
__device__ __forceinline__ void mma16816(float* d, const unsigned* a, const unsigned* b) {
    asm volatile(
        "mma.sync.aligned.m16n8k16.row.col.f32.f16.f16.f32 "
        "{%0,%1,%2,%3}, {%4,%5,%6,%7}, {%8,%9}, {%0,%1,%2,%3};"
        : "+f"(d[0]), "+f"(d[1]), "+f"(d[2]), "+f"(d[3])
        : "r"(a[0]), "r"(a[1]), "r"(a[2]), "r"(a[3]),
          "r"(b[0]), "r"(b[1]));
}

// ---------------- kernel 1: normalize + transpose (MLP-4 float4 loads) -------
__global__ __launch_bounds__(256) void k_norm_t(const float* __restrict__ in) {
    extern __shared__ float smn[];
    float*  s_tile = smn;                         // CC * 36 floats
    float*  s_red  = s_tile + CC*TSTR;            // 8 * 36
    float*  s_inv  = s_red + 8*TSTR;              // 32
    __half* s_half = reinterpret_cast<__half*>(s_inv + 32);   // 32 * 264 halves

    const int tid = threadIdx.x;
    const int tx = tid & 31;
    const int ty = tid >> 5;
    const int blocksPerBatch = NN/32;
    const int b  = blockIdx.x / blocksPerBatch;
    const int n0 = (blockIdx.x % blocksPerBatch) * 32;

    if (blockIdx.x == 0 && tid < 3) g_acc[tid] = 0.0f;
    if (blockIdx.x == 0 && tid == 3) g_done = 0;

    // ---- phase A: buffered float4 loads (MLP=4) + fused sum-of-squares ----
    const float* src = in + b*CC*NN + n0;
    const int pxg = tid & 7;
    const int c0  = tid >> 3;
    float ss0 = 0.f, ss1 = 0.f, ss2 = 0.f, ss3 = 0.f;
    #pragma unroll
    for (int half = 0; half < 2; half++) {
        float4 v[4];
        #pragma unroll
        for (int i = 0; i < 4; i++) {
            int c = (half*4 + i)*32 + c0;
            v[i] = __ldcs(reinterpret_cast<const float4*>(src + c*NN + pxg*4));
        }
        #pragma unroll
        for (int i = 0; i < 4; i++) {
            int c = (half*4 + i)*32 + c0;
            *reinterpret_cast<float4*>(&s_tile[c*TSTR + pxg*4]) = v[i];
            ss0 += v[i].x*v[i].x; ss1 += v[i].y*v[i].y;
            ss2 += v[i].z*v[i].z; ss3 += v[i].w*v[i].w;
        }
    }
    #pragma unroll
    for (int o = 8; o <= 16; o <<= 1) {
        ss0 += __shfl_xor_sync(0xffffffffu, ss0, o);
        ss1 += __shfl_xor_sync(0xffffffffu, ss1, o);
        ss2 += __shfl_xor_sync(0xffffffffu, ss2, o);
        ss3 += __shfl_xor_sync(0xffffffffu, ss3, o);
    }
    if (tx < 8) {
        *reinterpret_cast<float4*>(&s_red[ty*TSTR + tx*4]) =
            make_float4(ss0, ss1, ss2, ss3);
    }
    __syncthreads();
    if (tid < 32) {
        float t = 0.0f;
        #pragma unroll
        for (int w = 0; w < 8; w++) t += s_red[w*TSTR + tid];
        s_inv[tid] = 1.0f / fmaxf(sqrtf(t), 1e-12f);
    }
    __syncthreads();

    // ---- phase B: scale + fp16 pack, lane = pixel (conflict-free) ----
    {
        const int px = tx;
        float inv = s_inv[px];
        uint4* hrow = reinterpret_cast<uint4*>(s_half) + px*ROWQ;
        #pragma unroll
        for (int cc2 = 0; cc2 < 4; cc2++) {
            int ch = ty*4 + cc2;
            float v[8];
            #pragma unroll
            for (int j = 0; j < 8; j++) v[j] = s_tile[(ch*8 + j)*TSTR + px] * inv;
            uint4 q;
            __half2 h;
            h = __floats2half2_rn(v[0], v[1]); q.x = *reinterpret_cast<unsigned*>(&h);
            h = __floats2half2_rn(v[2], v[3]); q.y = *reinterpret_cast<unsigned*>(&h);
            h = __floats2half2_rn(v[4], v[5]); q.z = *reinterpret_cast<unsigned*>(&h);
            h = __floats2half2_rn(v[6], v[7]); q.w = *reinterpret_cast<unsigned*>(&h);
            hrow[ch] = q;
        }
    }
    __syncthreads();

    // ---- phase C: coalesced uint4 copy smem -> global ----
    {
        uint4* dst = reinterpret_cast<uint4*>(g_rgbTh + (size_t)(b*NN + n0)*CC);
        const uint4* srcq = reinterpret_cast<const uint4*>(s_half);
        const int cb = tid & 31;
        const int pq = tid >> 5;
        #pragma unroll
        for (int it = 0; it < 4; it++) {
            int px = it*8 + pq;
            dst[px*(CC/8) + cb] = srcq[px*ROWQ + cb];
        }
    }
}

// ---------------- kernel 2: main pass (32 px tiles, 4 blocks/SM) -------------
__device__ __forceinline__ int corner_idx(int xx, int yy, float& w) {
    bool v = (xx >= 0) & (xx < WW) & (yy >= 0) & (yy < HH);
    if (!v) w = 0.0f;
    int cx = min(max(xx, 0), WW-1);
    int cy = min(max(yy, 0), HH-1);
    return cy*WW + cx;
}

__global__ __launch_bounds__(256) void k_main(const float* __restrict__ dep,
                                              const float* __restrict__ proj,
                                              const int*   __restrict__ rand_idx,
                                              const float* __restrict__ valid) {
    extern __shared__ float sm[];
    __half* s_depH  = reinterpret_cast<__half*>(sm);     // hi: 32*264 halves
    __half* s_depL  = s_depH + 32*ROWQ*8;                // lo: 32*264 halves
    __half* s_randH = s_depL + 32*ROWQ*8;                // 32*264 halves
    float*  s_sim   = reinterpret_cast<float*>(s_randH + 32*ROWQ*8); // 32*33
    float*  s_pos   = s_sim + NRAND*33;                  // 32
    float*  s_inv   = s_pos + 32;                        // 32
    float*  s_red   = s_inv + 32;                        // 8*33

    const int tid = threadIdx.x;
    const int tx  = tid & 31;
    const int ty  = tid >> 5;                  // warp id 0..7
    const int b  = blockIdx.x >> 9;            // 512 blocks per batch
    const int n0 = (blockIdx.x & 511) * 32;

    // ---- stage dep tile split fp16 hi/lo, MLP-16 buffered loads ----
    {
        const int px = tx;
        const int cg = ty;                     // chunks cg*4..cg*4+3
        const float* dsrc = dep + b*CC*NN + n0 + px;
        float ss = 0.0f;
        uint4* hrow = reinterpret_cast<uint4*>(s_depH) + px*ROWQ;
        uint4* lrow = reinterpret_cast<uint4*>(s_depL) + px*ROWQ;
        #pragma unroll
        for (int jj = 0; jj < 2; jj++) {
            float v[16];
            #pragma unroll
            for (int t = 0; t < 16; t++)
                v[t] = __ldcs(&dsrc[((cg*4 + jj*2)*8 + t)*NN]);
            #pragma unroll
            for (int j2 = 0; j2 < 2; j2++) {
                int chunk = cg*4 + jj*2 + j2;
                const float* vv = v + j2*8;
                __half hi[8], lo[8];
                #pragma unroll
                for (int t = 0; t < 8; t++) {
                    ss += vv[t]*vv[t];
                    hi[t] = __float2half_rn(vv[t]);
                    lo[t] = __float2half_rn(vv[t] - __half2float(hi[t]));
                }
                uint4 qh, ql;
                __half2 h;
                h = __halves2half2(hi[0], hi[1]); qh.x = *reinterpret_cast<unsigned*>(&h);
                h = __halves2half2(hi[2], hi[3]); qh.y = *reinterpret_cast<unsigned*>(&h);
                h = __halves2half2(hi[4], hi[5]); qh.z = *reinterpret_cast<unsigned*>(&h);
                h = __halves2half2(hi[6], hi[7]); qh.w = *reinterpret_cast<unsigned*>(&h);
                h = __halves2half2(lo[0], lo[1]); ql.x = *reinterpret_cast<unsigned*>(&h);
                h = __halves2half2(lo[2], lo[3]); ql.y = *reinterpret_cast<unsigned*>(&h);
                h = __halves2half2(lo[4], lo[5]); ql.z = *reinterpret_cast<unsigned*>(&h);
                h = __halves2half2(lo[6], lo[7]); ql.w = *reinterpret_cast<unsigned*>(&h);
                hrow[chunk] = qh;
                lrow[chunk] = ql;
            }
        }
        s_red[cg*33 + px] = ss;
    }
    // ---- stage rand vectors (fp16 rows, padded) ----
    {
        int k = tid >> 3, part = tid & 7;
        int ridx = rand_idx[b*NRAND + k];
        const uint4* row = reinterpret_cast<const uint4*>(g_rgbTh + (size_t)(b*NN + ridx)*CC);
        uint4* drow = reinterpret_cast<uint4*>(s_randH) + k*ROWQ;
        #pragma unroll
        for (int i = 0; i < 4; i++) {
            int chunk = part + 8*i;
            drow[chunk] = row[chunk];
        }
    }
    __syncthreads();
    if (tid < 32) {
        float t = 0.0f;
        #pragma unroll
        for (int w = 0; w < 8; w++) t += s_red[w*33 + tid];
        s_inv[tid] = 1.0f / fmaxf(sqrtf(t), 1e-12f);
    }
    __syncthreads();

    // ---- phase 3: rand GEMM on tensor cores, hi+lo, K split across warps ----
    {
        unsigned aHBase = (unsigned)__cvta_generic_to_shared(s_depH);
        unsigned aLBase = (unsigned)__cvta_generic_to_shared(s_depL);
        unsigned bBase  = (unsigned)__cvta_generic_to_shared(s_randH);
        const int pxb = (ty & 1) * 16;
        const int kb0 = ((ty >> 1) & 1) * 16;
        const int kh  = ty >> 2;               // K-half 0/1
        const unsigned aRow = (unsigned)(pxb + (tx & 15)) * ROWQ + (unsigned)(tx >> 4);
        const unsigned bRow0 = (unsigned)(kb0 + (tx & 7)) * ROWQ + (unsigned)((tx >> 3) & 1);
        const unsigned bRow1 = bRow0 + 8u*ROWQ;
        float d0[4] = {0,0,0,0}, d1[4] = {0,0,0,0};
        #pragma unroll
        for (int kk = 0; kk < 8; kk++) {
            int ck = kh*8 + kk;
            unsigned ah[4], al[4], b0r[2], b1r[2];
            ldmx4(ah,  aHBase + (aRow  + 2*ck) * 16);
            ldmx4(al,  aLBase + (aRow  + 2*ck) * 16);
            ldmx2(b0r, bBase  + (bRow0 + 2*ck) * 16);
            ldmx2(b1r, bBase  + (bRow1 + 2*ck) * 16);
            mma16816(d0, ah, b0r);
            mma16816(d0, al, b0r);
            mma16816(d1, ah, b1r);
            mma16816(d1, al, b1r);
        }
        int pxl = pxb + (tx >> 2);
        int kl  = (tx & 3) * 2;
        if (kh == 0) {
            s_sim[(kb0 + kl + 0)*33 + pxl]     = d0[0];
            s_sim[(kb0 + kl + 1)*33 + pxl]     = d0[1];
            s_sim[(kb0 + kl + 0)*33 + pxl + 8] = d0[2];
            s_sim[(kb0 + kl + 1)*33 + pxl + 8] = d0[3];
            s_sim[(kb0 + 8 + kl + 0)*33 + pxl]     = d1[0];
            s_sim[(kb0 + 8 + kl + 1)*33 + pxl]     = d1[1];
            s_sim[(kb0 + 8 + kl + 0)*33 + pxl + 8] = d1[2];
            s_sim[(kb0 + 8 + kl + 1)*33 + pxl + 8] = d1[3];
        }
        __syncthreads();
        if (kh == 1) {
            s_sim[(kb0 + kl + 0)*33 + pxl]     += d0[0];
            s_sim[(kb0 + kl + 1)*33 + pxl]     += d0[1];
            s_sim[(kb0 + kl + 0)*33 + pxl + 8] += d0[2];
            s_sim[(kb0 + kl + 1)*33 + pxl + 8] += d0[3];
            s_sim[(kb0 + 8 + kl + 0)*33 + pxl]     += d1[0];
            s_sim[(kb0 + 8 + kl + 1)*33 + pxl]     += d1[1];
            s_sim[(kb0 + 8 + kl + 0)*33 + pxl + 8] += d1[2];
            s_sim[(kb0 + 8 + kl + 1)*33 + pxl + 8] += d1[3];
        }
    }

    // ---- phase 2: pos_sim (warp handles 4 pixels), dep = hi + lo ----
    const float* projU = proj + b*2*NN;
    const float* projV = projU + NN;
    const uint4* depHQ = reinterpret_cast<const uint4*>(s_depH);
    const uint4* depLQ = reinterpret_cast<const uint4*>(s_depL);
    #pragma unroll
    for (int q = 0; q < 4; q++) {
        int px = ty*4 + q;
        int n  = n0 + px;
        float pu = projU[n], pv = projV[n];
        float x0f = floorf(pu), y0f = floorf(pv);
        float wx = pu - x0f, wy = pv - y0f;
        int x0 = (int)x0f, y0 = (int)y0f;
        float w00 = (1.0f-wx)*(1.0f-wy), w10 = wx*(1.0f-wy);
        float w01 = (1.0f-wx)*wy,        w11 = wx*wy;
        int i00 = corner_idx(x0,   y0,   w00);
        int i10 = corner_idx(x0+1, y0,   w10);
        int i01 = corner_idx(x0,   y0+1, w01);
        int i11 = corner_idx(x0+1, y0+1, w11);
        const uint4* r00 = reinterpret_cast<const uint4*>(g_rgbTh + (size_t)(b*NN + i00)*CC);
        const uint4* r10 = reinterpret_cast<const uint4*>(g_rgbTh + (size_t)(b*NN + i10)*CC);
        const uint4* r01 = reinterpret_cast<const uint4*>(g_rgbTh + (size_t)(b*NN + i01)*CC);
        const uint4* r11 = reinterpret_cast<const uint4*>(g_rgbTh + (size_t)(b*NN + i11)*CC);
        uint4 dqh = depHQ[px*ROWQ + tx];
        uint4 dql = depLQ[px*ROWQ + tx];
        uint4 q00 = r00[tx], q10 = r10[tx], q01 = r01[tx], q11 = r11[tx];
        float pacc = 0.0f;
        const unsigned* duh = &dqh.x;
        const unsigned* dul = &dql.x;
        const unsigned* u00 = &q00.x;
        const unsigned* u10 = &q10.x;
        const unsigned* u01 = &q01.x;
        const unsigned* u11 = &q11.x;
        #pragma unroll
        for (int j = 0; j < 4; j++) {
            float2 dh = __half22float2(*reinterpret_cast<const __half2*>(&duh[j]));
            float2 dl = __half22float2(*reinterpret_cast<const __half2*>(&dul[j]));
            float dx = dh.x + dl.x, dy = dh.y + dl.y;
            float2 a00 = __half22float2(*reinterpret_cast<const __half2*>(&u00[j]));
            float2 a10 = __half22float2(*reinterpret_cast<const __half2*>(&u10[j]));
            float2 a01 = __half22float2(*reinterpret_cast<const __half2*>(&u01[j]));
            float2 a11 = __half22float2(*reinterpret_cast<const __half2*>(&u11[j]));
            pacc += dx*(w00*a00.x + w10*a10.x + w01*a01.x + w11*a11.x);
            pacc += dy*(w00*a00.y + w10*a10.y + w01*a01.y + w11*a11.y);
        }
        #pragma unroll
        for (int o = 16; o; o >>= 1) pacc += __shfl_xor_sync(0xffffffffu, pacc, o);
        if (tx == 0) s_pos[px] = pacc;
    }

    // ---- grid-point dep dump (hi+lo -> fp32, normalized * TEMP_INV) ----
    const int v_row = n0 >> 7;
    const int u0 = n0 & 127;
    const bool gridRow = ((v_row & 7) == 0);
    if (gridRow && ty < 4) {
        int px = ty*8;     // grid pixels 0,8,16,24
        int p = ((v_row >> 3) << 4) + ((u0 + px) >> 3);
        float sc = s_inv[px] * TEMP_INV;
        float* dst = g_depGrid + (b*NPOS + p)*CC;
        uint4 dqh = depHQ[px*ROWQ + tx];
        uint4 dql = depLQ[px*ROWQ + tx];
        const unsigned* duh = &dqh.x;
        const unsigned* dul = &dql.x;
        float4 o0, o1;
        float2 fh, fl;
        fh = __half22float2(*reinterpret_cast<const __half2*>(&duh[0]));
        fl = __half22float2(*reinterpret_cast<const __half2*>(&dul[0]));
        o0.x = (fh.x+fl.x)*sc; o0.y = (fh.y+fl.y)*sc;
        fh = __half22float2(*reinterpret_cast<const __half2*>(&duh[1]));
        fl = __half22float2(*reinterpret_cast<const __half2*>(&dul[1]));
        o0.z = (fh.x+fl.x)*sc; o0.w = (fh.y+fl.y)*sc;
        fh = __half22float2(*reinterpret_cast<const __half2*>(&duh[2]));
        fl = __half22float2(*reinterpret_cast<const __half2*>(&dul[2]));
        o1.x = (fh.x+fl.x)*sc; o1.y = (fh.y+fl.y)*sc;
        fh = __half22float2(*reinterpret_cast<const __half2*>(&duh[3]));
        fl = __half22float2(*reinterpret_cast<const __half2*>(&dul[3]));
        o1.z = (fh.x+fl.x)*sc; o1.w = (fh.y+fl.y)*sc;
        reinterpret_cast<float4*>(dst + tx*8)[0] = o0;
        reinterpret_cast<float4*>(dst + tx*8)[1] = o1;
    }
    __syncthreads();

    // ---- phase 4: logsumexp / max + fused loss for non-grid pixels ----
    float wl = 0.0f, wm = 0.0f, wc = 0.0f;
    #pragma unroll
    for (int q = 0; q < 4; q++) {
        int px = ty*4 + q;
        float scale = s_inv[px] * TEMP_INV;
        float pos = s_pos[px] * scale;
        float v = s_sim[tx*33 + px] * scale;
        float mneg = v;
        #pragma unroll
        for (int o = 16; o; o >>= 1) mneg = fmaxf(mneg, __shfl_xor_sync(0xffffffffu, mneg, o));
        float m = fmaxf(pos, mneg);
        float e = expf(v - m);
        #pragma unroll
        for (int o = 16; o; o >>= 1) e += __shfl_xor_sync(0xffffffffu, e, o);
        if (tx == 0) {
            float lse = m + logf(e + expf(pos - m));
            bool isGrid = gridRow && (q == 0) && ((ty & 1) == 0);  // px%8==0
            if (isGrid) {
                int p = ((v_row >> 3) << 4) + ((u0 + px) >> 3);
                g_posG[b*NPOS + p] = pos;
                g_lseG[b*NPOS + p] = lse;
                g_mxG [b*NPOS + p] = mneg;
            } else {
                float mask = valid[b*NN + n0 + px];
                wl += (lse - pos) * mask;
                wm += mask;
                wc += (pos > mneg && mask > 0.5f) ? 1.0f : 0.0f;
            }
        }
    }
    __syncthreads();
    if (tx == 0) {
        s_red[ty] = wl;
        s_red[8 + ty] = wm;
        s_red[16 + ty] = wc;
    }
    __syncthreads();
    if (tid == 0) {
        float a = 0.f, b2 = 0.f, c2 = 0.f;
        #pragma unroll
        for (int j = 0; j < 8; j++) { a += s_red[j]; b2 += s_red[8+j]; c2 += s_red[16+j]; }
        atomicAdd(&g_acc[0], a);
        atomicAdd(&g_acc[1], b2);
        atomicAdd(&g_acc[2], c2);
    }
}

// ---------------- kernel 3: hard negatives + grid-pixel loss + epilogue ------
__global__ __launch_bounds__(256) void k_hard(const float* __restrict__ proj,
                                              const int*   __restrict__ offu,
                                              const int*   __restrict__ offv,
                                              const float* __restrict__ valid,
                                              float* __restrict__ out) {
    __shared__ float s_depv[CC];
    __shared__ float s_hsim[NHARD];
    const int tid = threadIdx.x;
    const int tx = tid & 31;
    const int ty = tid >> 5;
    const int b = blockIdx.x >> 8;
    const int p = blockIdx.x & 255;
    const int gh = (p >> 4) * 8;
    const int gw = (p & 15) * 8;
    const int ng = gh*WW + gw;

    s_depv[tid] = g_depGrid[(b*NPOS + p)*CC + tid];
    __syncthreads();

    float pu = proj[b*2*NN + ng];
    float pv = proj[b*2*NN + NN + ng];
    int posu = (int)fminf(fmaxf(pu, 0.0f), (float)(WW-1));
    int posv = (int)fminf(fmaxf(pv, 0.0f), (float)(HH-1));

    const uint4* r[12];
    #pragma unroll
    for (int j = 0; j < 12; j++) {
        int h = ty*12 + j;
        int ou = offu[(b*NHARD + h)*NPOS + p];
        int ov = offv[(b*NHARD + h)*NPOS + p];
        if (ou == 0 && ov == 0) ou = 1;
        int hu = min(max(posu + ou, 0), WW-1);
        int hv = min(max(posv + ov, 0), HH-1);
        r[j] = reinterpret_cast<const uint4*>(g_rgbTh + (size_t)(b*NN + hv*WW + hu)*CC);
    }
    uint4 q[12];
    #pragma unroll
    for (int j = 0; j < 12; j++) q[j] = r[j][tx];

    const float4* dv = reinterpret_cast<const float4*>(s_depv);
    float4 d0 = dv[2*tx];
    float4 d1 = dv[2*tx + 1];
    float acc[12];
    #pragma unroll
    for (int j = 0; j < 12; j++) {
        float2 f0 = __half22float2(*reinterpret_cast<__half2*>(&q[j].x));
        float2 f1 = __half22float2(*reinterpret_cast<__half2*>(&q[j].y));
        float2 f2 = __half22float2(*reinterpret_cast<__half2*>(&q[j].z));
        float2 f3 = __half22float2(*reinterpret_cast<__half2*>(&q[j].w));
        float a = 0.0f;
        a += d0.x*f0.x; a += d0.y*f0.y; a += d0.z*f1.x; a += d0.w*f1.y;
        a += d1.x*f2.x; a += d1.y*f2.y; a += d1.z*f3.x; a += d1.w*f3.y;
        acc[j] = a;
    }
    #pragma unroll
    for (int o = 16; o; o >>= 1) {
        #pragma unroll
        for (int j = 0; j < 12; j++)
            acc[j] += __shfl_xor_sync(0xffffffffu, acc[j], o);
    }
    if (tx == 0) {
        #pragma unroll
        for (int j = 0; j < 12; j++) s_hsim[ty*12 + j] = acc[j];
    }
    __syncthreads();

    if (tid < 32) {
        float v0 = s_hsim[tx];
        float v1 = s_hsim[tx + 32];
        float v2 = s_hsim[tx + 64];
        float m = fmaxf(fmaxf(v0, v1), v2);
        #pragma unroll
        for (int o = 16; o; o >>= 1) m = fmaxf(m, __shfl_xor_sync(0xffffffffu, m, o));
        float se = expf(v0 - m) + expf(v1 - m) + expf(v2 - m);
        #pragma unroll
        for (int o = 16; o; o >>= 1) se += __shfl_xor_sync(0xffffffffu, se, o);
        if (tx == 0) {
            float lse_h = m + logf(se);
            int bp = b*NPOS + p;
            float pos = g_posG[bp];
            float lse0 = g_lseG[bp];
            float mx0 = g_mxG[bp];
            float mm = fmaxf(lse0, lse_h);
            float lse = mm + logf(expf(lse0 - mm) + expf(lse_h - mm));
            float mx = fmaxf(mx0, m);
            float mask = valid[b*NN + ng];
            float lossp = (lse - pos) * mask;
            float corr = (pos > mx && mask > 0.5f) ? 1.0f : 0.0f;
            atomicAdd(&g_acc[0], lossp);
            atomicAdd(&g_acc[1], mask);
            atomicAdd(&g_acc[2], corr);
            __threadfence();
            unsigned t = atomicAdd(&g_done, 1u);
            if (t == (unsigned)(BB*NPOS) - 1u) {
                __threadfence();
                float denom = fmaxf(g_acc[1], 1.0f);
                out[0] = g_acc[0] / denom;
                out[1] = g_acc[2] / denom * 100.0f;
            }
        }
    }
}

// ---------------- launch -------------------------------------------------------
extern "C" void kernel_launch(void* const* d_in, const int* in_sizes, int n_in,
                              void* d_out, int out_size) {
    const float* rgb   = (const float*)d_in[0];
    const float* dep   = (const float*)d_in[1];
    const float* proj  = (const float*)d_in[2];
    const float* valid = (const float*)d_in[3];
    const int*   ridx  = (const int*)d_in[4];
    const int*   offu  = (const int*)d_in[5];
    const int*   offv  = (const int*)d_in[6];
    float* out = (float*)d_out;

    const int smem_norm = (CC*TSTR + 8*TSTR + 32) * (int)sizeof(float) + 32*ROWQ*16;
    cudaFuncSetAttribute(k_norm_t, cudaFuncAttributeMaxDynamicSharedMemorySize, smem_norm);

    const int smem_main = 32*ROWQ*16*3
                        + (NRAND*33 + 32 + 32 + 8*33) * (int)sizeof(float);
    cudaFuncSetAttribute(k_main, cudaFuncAttributeMaxDynamicSharedMemorySize, smem_main);

    k_norm_t<<<BB*NN/32, 256, smem_norm>>>(rgb);
    k_main<<<BB*NN/32, 256, smem_main>>>(dep, proj, ridx, valid);
    k_hard<<<BB*NPOS, 256>>>(proj, offu, offv, valid, out);
}

// round 15
// speedup vs baseline: 1.5078x; 1.0118x over previous
#include <cuda_runtime.h>
#include <cuda_fp16.h>
#include <math.h>

#define BB 8
#define CC 256
#define HH 128
#define WW 128
#define NN (HH*WW)          // 16384
#define NPOS 256
#define NHARD 96
#define NRAND 32
#define TEMP_INV (1.0f/0.07f)

#define ROWQ 33             // quads (16B units) per padded fp16 row (264 halves)

// ---------------- scratch (static device globals; no allocation) ------------
__device__ __half g_rgbTh[BB*NN*CC];    // normalized rgb (fp16), [b][px][ch]
__device__ float g_depGrid[BB*NPOS*CC]; // normalized*TEMP_INV dep at grid pts
__device__ float g_posG[BB*NPOS];       // pos_sim at grid points
__device__ float g_lseG[BB*NPOS];       // base lse at grid points
__device__ float g_mxG[BB*NPOS];        // rand max at grid points
__device__ float g_acc[3];              // loss_sum, mask_sum, correct_sum
__device__ unsigned g_done;

// ---------------- mma/ldmatrix helpers ---------------------------------------
__device__ __forceinline__ void ldmx4(unsigned* r, unsigned addr) {
    asm volatile("ldmatrix.sync.aligned.m8n8.x4.shared.b16 {%0,%1,%2,%3}, [%4];"
                 : "=r"(r[0]), "=r"(r[1]), "=r"(r[2]), "=r"(r[3]) : "r"(addr));
}
__device__ __forceinline__ void ldmx2(unsigned* r, unsigned addr) {
    asm volatile("ldmatrix.sync.aligned.m8n8.x2.shared.b16 {%0,%1}, [%2];"
                 : "=r"(r[0]), "=r"(r[1]) : "r"(addr));
}
__device__ __forceinline__ void mma16816(float* d, const unsigned* a, const unsigned* b) {
    asm volatile(
        "mma.sync.aligned.m16n8k16.row.col.f32.f16.f16.f32 "
        "{%0,%1,%2,%3}, {%4,%5,%6,%7}, {%8,%9}, {%0,%1,%2,%3};"
        : "+f"(d[0]), "+f"(d[1]), "+f"(d[2]), "+f"(d[3])
        : "r"(a[0]), "r"(a[1]), "r"(a[2]), "r"(a[3]),
          "r"(b[0]), "r"(b[1]));
}

// ---------------- kernel 1: normalize + transpose (low-smem, 8 blocks/SM) ----
__global__ __launch_bounds__(256) void k_norm_t(const float* __restrict__ in) {
    extern __shared__ float smn[];
    float*  s_red  = smn;                          // 8 * 36
    float*  s_inv  = s_red + 8*36;                 // 32
    __half* s_half = reinterpret_cast<__half*>(s_inv + 32);  // 32 * 264 halves

    const int tid = threadIdx.x;
    const int tx = tid & 31;
    const int ty = tid >> 5;
    const int blocksPerBatch = NN/32;
    const int b  = blockIdx.x / blocksPerBatch;
    const int n0 = (blockIdx.x % blocksPerBatch) * 32;

    if (blockIdx.x == 0 && tid < 3) g_acc[tid] = 0.0f;
    if (blockIdx.x == 0 && tid == 3) g_done = 0;

    // ---- pass 1: float4 read + sum-of-squares only (no staging) ----
    const float* src = in + b*CC*NN + n0;
    const int pxg = tid & 7;
    const int c0  = tid >> 3;
    float ss0 = 0.f, ss1 = 0.f, ss2 = 0.f, ss3 = 0.f;
    #pragma unroll
    for (int half = 0; half < 2; half++) {
        float4 v[4];
        #pragma unroll
        for (int i = 0; i < 4; i++) {
            int c = (half*4 + i)*32 + c0;
            v[i] = *reinterpret_cast<const float4*>(src + c*NN + pxg*4);
        }
        #pragma unroll
        for (int i = 0; i < 4; i++) {
            ss0 += v[i].x*v[i].x; ss1 += v[i].y*v[i].y;
            ss2 += v[i].z*v[i].z; ss3 += v[i].w*v[i].w;
        }
    }
    #pragma unroll
    for (int o = 8; o <= 16; o <<= 1) {
        ss0 += __shfl_xor_sync(0xffffffffu, ss0, o);
        ss1 += __shfl_xor_sync(0xffffffffu, ss1, o);
        ss2 += __shfl_xor_sync(0xffffffffu, ss2, o);
        ss3 += __shfl_xor_sync(0xffffffffu, ss3, o);
    }
    if (tx < 8) {
        *reinterpret_cast<float4*>(&s_red[ty*36 + tx*4]) =
            make_float4(ss0, ss1, ss2, ss3);
    }
    __syncthreads();
    if (tid < 32) {
        float t = 0.0f;
        #pragma unroll
        for (int w = 0; w < 8; w++) t += s_red[w*36 + tid];
        s_inv[tid] = 1.0f / fmaxf(sqrtf(t), 1e-12f);
    }
    __syncthreads();

    // ---- pass 2: re-read from L2 (coalesced), scale + fp16 pack ----
    {
        const int px = tx;
        float inv = s_inv[px];
        uint4* hrow = reinterpret_cast<uint4*>(s_half) + px*ROWQ;
        #pragma unroll
        for (int cc2 = 0; cc2 < 4; cc2++) {
            int ch = ty*4 + cc2;
            float v[8];
            #pragma unroll
            for (int j = 0; j < 8; j++)
                v[j] = src[(ch*8 + j)*NN + px];   // 128B coalesced, L2-hot
            uint4 q;
            __half2 h;
            h = __floats2half2_rn(v[0]*inv, v[1]*inv); q.x = *reinterpret_cast<unsigned*>(&h);
            h = __floats2half2_rn(v[2]*inv, v[3]*inv); q.y = *reinterpret_cast<unsigned*>(&h);
            h = __floats2half2_rn(v[4]*inv, v[5]*inv); q.z = *reinterpret_cast<unsigned*>(&h);
            h = __floats2half2_rn(v[6]*inv, v[7]*inv); q.w = *reinterpret_cast<unsigned*>(&h);
            hrow[ch] = q;
        }
    }
    __syncthreads();

    // ---- pass 3: coalesced uint4 copy smem -> global ----
    {
        uint4* dst = reinterpret_cast<uint4*>(g_rgbTh + (size_t)(b*NN + n0)*CC);
        const uint4* srcq = reinterpret_cast<const uint4*>(s_half);
        const int cb = tid & 31;
        const int pq = tid >> 5;
        #pragma unroll
        for (int it = 0; it < 4; it++) {
            int px = it*8 + pq;
            dst[px*(CC/8) + cb] = srcq[px*ROWQ + cb];
        }
    }
}

// ---------------- kernel 2: main pass (32 px tiles, 4 blocks/SM) -------------
__device__ __forceinline__ int corner_idx(int xx, int yy, float& w) {
    bool v = (xx >= 0) & (xx < WW) & (yy >= 0) & (yy < HH);
    if (!v) w = 0.0f;
    int cx = min(max(xx, 0), WW-1);
    int cy = min(max(yy, 0), HH-1);
    return cy*WW + cx;
}

__global__ __launch_bounds__(256) void k_main(const float* __restrict__ dep,
                                              const float* __restrict__ proj,
                                              const int*   __restrict__ rand_idx,
                                              const float* __restrict__ valid) {
    extern __shared__ float sm[];
    __half* s_depH  = reinterpret_cast<__half*>(sm);     // hi: 32*264 halves
    __half* s_depL  = s_depH + 32*ROWQ*8;                // lo: 32*264 halves
    __half* s_randH = s_depL + 32*ROWQ*8;                // 32*264 halves
    float*  s_sim   = reinterpret_cast<float*>(s_randH + 32*ROWQ*8); // 32*33
    float*  s_pos   = s_sim + NRAND*33;                  // 32
    float*  s_inv   = s_pos + 32;                        // 32
    float*  s_red   = s_inv + 32;                        // 8*33

    const int tid = threadIdx.x;
    const int tx  = tid & 31;
    const int ty  = tid >> 5;                  // warp id 0..7
    const int b  = blockIdx.x >> 9;            // 512 blocks per batch
    const int n0 = (blockIdx.x & 511) * 32;

    // ---- stage dep tile split fp16 hi/lo, MLP-16 buffered loads ----
    {
        const int px = tx;
        const int cg = ty;                     // chunks cg*4..cg*4+3
        const float* dsrc = dep + b*CC*NN + n0 + px;
        float ss = 0.0f;
        uint4* hrow = reinterpret_cast<uint4*>(s_depH) + px*ROWQ;
        uint4* lrow = reinterpret_cast<uint4*>(s_depL) + px*ROWQ;
        #pragma unroll
        for (int jj = 0; jj < 2; jj++) {
            float v[16];
            #pragma unroll
            for (int t = 0; t < 16; t++)
                v[t] = __ldcs(&dsrc[((cg*4 + jj*2)*8 + t)*NN]);
            #pragma unroll
            for (int j2 = 0; j2 < 2; j2++) {
                int chunk = cg*4 + jj*2 + j2;
                const float* vv = v + j2*8;
                __half hi[8], lo[8];
                #pragma unroll
                for (int t = 0; t < 8; t++) {
                    ss += vv[t]*vv[t];
                    hi[t] = __float2half_rn(vv[t]);
                    lo[t] = __float2half_rn(vv[t] - __half2float(hi[t]));
                }
                uint4 qh, ql;
                __half2 h;
                h = __halves2half2(hi[0], hi[1]); qh.x = *reinterpret_cast<unsigned*>(&h);
                h = __halves2half2(hi[2], hi[3]); qh.y = *reinterpret_cast<unsigned*>(&h);
                h = __halves2half2(hi[4], hi[5]); qh.z = *reinterpret_cast<unsigned*>(&h);
                h = __halves2half2(hi[6], hi[7]); qh.w = *reinterpret_cast<unsigned*>(&h);
                h = __halves2half2(lo[0], lo[1]); ql.x = *reinterpret_cast<unsigned*>(&h);
                h = __halves2half2(lo[2], lo[3]); ql.y = *reinterpret_cast<unsigned*>(&h);
                h = __halves2half2(lo[4], lo[5]); ql.z = *reinterpret_cast<unsigned*>(&h);
                h = __halves2half2(lo[6], lo[7]); ql.w = *reinterpret_cast<unsigned*>(&h);
                hrow[chunk] = qh;
                lrow[chunk] = ql;
            }
        }
        s_red[cg*33 + px] = ss;
    }
    // ---- stage rand vectors (fp16 rows, padded) ----
    {
        int k = tid >> 3, part = tid & 7;
        int ridx = rand_idx[b*NRAND + k];
        const uint4* row = reinterpret_cast<const uint4*>(g_rgbTh + (size_t)(b*NN + ridx)*CC);
        uint4* drow = reinterpret_cast<uint4*>(s_randH) + k*ROWQ;
        #pragma unroll
        for (int i = 0; i < 4; i++) {
            int chunk = part + 8*i;
            drow[chunk] = row[chunk];
        }
    }
    __syncthreads();
    if (tid < 32) {
        float t = 0.0f;
        #pragma unroll
        for (int w = 0; w < 8; w++) t += s_red[w*33 + tid];
        s_inv[tid] = 1.0f / fmaxf(sqrtf(t), 1e-12f);
    }
    __syncthreads();

    // ---- phase 3: rand GEMM on tensor cores, hi+lo, K split across warps ----
    {
        unsigned aHBase = (unsigned)__cvta_generic_to_shared(s_depH);
        unsigned aLBase = (unsigned)__cvta_generic_to_shared(s_depL);
        unsigned bBase  = (unsigned)__cvta_generic_to_shared(s_randH);
        const int pxb = (ty & 1) * 16;
        const int kb0 = ((ty >> 1) & 1) * 16;
        const int kh  = ty >> 2;               // K-half 0/1
        const unsigned aRow = (unsigned)(pxb + (tx & 15)) * ROWQ + (unsigned)(tx >> 4);
        const unsigned bRow0 = (unsigned)(kb0 + (tx & 7)) * ROWQ + (unsigned)((tx >> 3) & 1);
        const unsigned bRow1 = bRow0 + 8u*ROWQ;
        float d0[4] = {0,0,0,0}, d1[4] = {0,0,0,0};
        #pragma unroll
        for (int kk = 0; kk < 8; kk++) {
            int ck = kh*8 + kk;
            unsigned ah[4], al[4], b0r[2], b1r[2];
            ldmx4(ah,  aHBase + (aRow  + 2*ck) * 16);
            ldmx4(al,  aLBase + (aRow  + 2*ck) * 16);
            ldmx2(b0r, bBase  + (bRow0 + 2*ck) * 16);
            ldmx2(b1r, bBase  + (bRow1 + 2*ck) * 16);
            mma16816(d0, ah, b0r);
            mma16816(d0, al, b0r);
            mma16816(d1, ah, b1r);
            mma16816(d1, al, b1r);
        }
        int pxl = pxb + (tx >> 2);
        int kl  = (tx & 3) * 2;
        if (kh == 0) {
            s_sim[(kb0 + kl + 0)*33 + pxl]     = d0[0];
            s_sim[(kb0 + kl + 1)*33 + pxl]     = d0[1];
            s_sim[(kb0 + kl + 0)*33 + pxl + 8] = d0[2];
            s_sim[(kb0 + kl + 1)*33 + pxl + 8] = d0[3];
            s_sim[(kb0 + 8 + kl + 0)*33 + pxl]     = d1[0];
            s_sim[(kb0 + 8 + kl + 1)*33 + pxl]     = d1[1];
            s_sim[(kb0 + 8 + kl + 0)*33 + pxl + 8] = d1[2];
            s_sim[(kb0 + 8 + kl + 1)*33 + pxl + 8] = d1[3];
        }
        __syncthreads();
        if (kh == 1) {
            s_sim[(kb0 + kl + 0)*33 + pxl]     += d0[0];
            s_sim[(kb0 + kl + 1)*33 + pxl]     += d0[1];
            s_sim[(kb0 + kl + 0)*33 + pxl + 8] += d0[2];
            s_sim[(kb0 + kl + 1)*33 + pxl + 8] += d0[3];
            s_sim[(kb0 + 8 + kl + 0)*33 + pxl]     += d1[0];
            s_sim[(kb0 + 8 + kl + 1)*33 + pxl]     += d1[1];
            s_sim[(kb0 + 8 + kl + 0)*33 + pxl + 8] += d1[2];
            s_sim[(kb0 + 8 + kl + 1)*33 + pxl + 8] += d1[3];
        }
    }

    // ---- phase 2: pos_sim (warp handles 4 pixels), dep = hi + lo ----
    const float* projU = proj + b*2*NN;
    const float* projV = projU + NN;
    const uint4* depHQ = reinterpret_cast<const uint4*>(s_depH);
    const uint4* depLQ = reinterpret_cast<const uint4*>(s_depL);
    #pragma unroll
    for (int q = 0; q < 4; q++) {
        int px = ty*4 + q;
        int n  = n0 + px;
        float pu = projU[n], pv = projV[n];
        float x0f = floorf(pu), y0f = floorf(pv);
        float wx = pu - x0f, wy = pv - y0f;
        int x0 = (int)x0f, y0 = (int)y0f;
        float w00 = (1.0f-wx)*(1.0f-wy), w10 = wx*(1.0f-wy);
        float w01 = (1.0f-wx)*wy,        w11 = wx*wy;
        int i00 = corner_idx(x0,   y0,   w00);
        int i10 = corner_idx(x0+1, y0,   w10);
        int i01 = corner_idx(x0,   y0+1, w01);
        int i11 = corner_idx(x0+1, y0+1, w11);
        const uint4* r00 = reinterpret_cast<const uint4*>(g_rgbTh + (size_t)(b*NN + i00)*CC);
        const uint4* r10 = reinterpret_cast<const uint4*>(g_rgbTh + (size_t)(b*NN + i10)*CC);
        const uint4* r01 = reinterpret_cast<const uint4*>(g_rgbTh + (size_t)(b*NN + i01)*CC);
        const uint4* r11 = reinterpret_cast<const uint4*>(g_rgbTh + (size_t)(b*NN + i11)*CC);
        uint4 dqh = depHQ[px*ROWQ + tx];
        uint4 dql = depLQ[px*ROWQ + tx];
        uint4 q00 = r00[tx], q10 = r10[tx], q01 = r01[tx], q11 = r11[tx];
        float pacc = 0.0f;
        const unsigned* duh = &dqh.x;
        const unsigned* dul = &dql.x;
        const unsigned* u00 = &q00.x;
        const unsigned* u10 = &q10.x;
        const unsigned* u01 = &q01.x;
        const unsigned* u11 = &q11.x;
        #pragma unroll
        for (int j = 0; j < 4; j++) {
            float2 dh = __half22float2(*reinterpret_cast<const __half2*>(&duh[j]));
            float2 dl = __half22float2(*reinterpret_cast<const __half2*>(&dul[j]));
            float dx = dh.x + dl.x, dy = dh.y + dl.y;
            float2 a00 = __half22float2(*reinterpret_cast<const __half2*>(&u00[j]));
            float2 a10 = __half22float2(*reinterpret_cast<const __half2*>(&u10[j]));
            float2 a01 = __half22float2(*reinterpret_cast<const __half2*>(&u01[j]));
            float2 a11 = __half22float2(*reinterpret_cast<const __half2*>(&u11[j]));
            pacc += dx*(w00*a00.x + w10*a10.x + w01*a01.x + w11*a11.x);
            pacc += dy*(w00*a00.y + w10*a10.y + w01*a01.y + w11*a11.y);
        }
        #pragma unroll
        for (int o = 16; o; o >>= 1) pacc += __shfl_xor_sync(0xffffffffu, pacc, o);
        if (tx == 0) s_pos[px] = pacc;
    }

    // ---- grid-point dep dump (hi+lo -> fp32, normalized * TEMP_INV) ----
    const int v_row = n0 >> 7;
    const int u0 = n0 & 127;
    const bool gridRow = ((v_row & 7) == 0);
    if (gridRow && ty < 4) {
        int px = ty*8;     // grid pixels 0,8,16,24
        int p = ((v_row >> 3) << 4) + ((u0 + px) >> 3);
        float sc = s_inv[px] * TEMP_INV;
        float* dst = g_depGrid + (b*NPOS + p)*CC;
        uint4 dqh = depHQ[px*ROWQ + tx];
        uint4 dql = depLQ[px*ROWQ + tx];
        const unsigned* duh = &dqh.x;
        const unsigned* dul = &dql.x;
        float4 o0, o1;
        float2 fh, fl;
        fh = __half22float2(*reinterpret_cast<const __half2*>(&duh[0]));
        fl = __half22float2(*reinterpret_cast<const __half2*>(&dul[0]));
        o0.x = (fh.x+fl.x)*sc; o0.y = (fh.y+fl.y)*sc;
        fh = __half22float2(*reinterpret_cast<const __half2*>(&duh[1]));
        fl = __half22float2(*reinterpret_cast<const __half2*>(&dul[1]));
        o0.z = (fh.x+fl.x)*sc; o0.w = (fh.y+fl.y)*sc;
        fh = __half22float2(*reinterpret_cast<const __half2*>(&duh[2]));
        fl = __half22float2(*reinterpret_cast<const __half2*>(&dul[2]));
        o1.x = (fh.x+fl.x)*sc; o1.y = (fh.y+fl.y)*sc;
        fh = __half22float2(*reinterpret_cast<const __half2*>(&duh[3]));
        fl = __half22float2(*reinterpret_cast<const __half2*>(&dul[3]));
        o1.z = (fh.x+fl.x)*sc; o1.w = (fh.y+fl.y)*sc;
        reinterpret_cast<float4*>(dst + tx*8)[0] = o0;
        reinterpret_cast<float4*>(dst + tx*8)[1] = o1;
    }
    __syncthreads();

    // ---- phase 4: logsumexp / max + fused loss for non-grid pixels ----
    float wl = 0.0f, wm = 0.0f, wc = 0.0f;
    #pragma unroll
    for (int q = 0; q < 4; q++) {
        int px = ty*4 + q;
        float scale = s_inv[px] * TEMP_INV;
        float pos = s_pos[px] * scale;
        float v = s_sim[tx*33 + px] * scale;
        float mneg = v;
        #pragma unroll
        for (int o = 16; o; o >>= 1) mneg = fmaxf(mneg, __shfl_xor_sync(0xffffffffu, mneg, o));
        float m = fmaxf(pos, mneg);
        float e = expf(v - m);
        #pragma unroll
        for (int o = 16; o; o >>= 1) e += __shfl_xor_sync(0xffffffffu, e, o);
        if (tx == 0) {
            float lse = m + logf(e + expf(pos - m));
            bool isGrid = gridRow && (q == 0) && ((ty & 1) == 0);  // px%8==0
            if (isGrid) {
                int p = ((v_row >> 3) << 4) + ((u0 + px) >> 3);
                g_posG[b*NPOS + p] = pos;
                g_lseG[b*NPOS + p] = lse;
                g_mxG [b*NPOS + p] = mneg;
            } else {
                float mask = valid[b*NN + n0 + px];
                wl += (lse - pos) * mask;
                wm += mask;
                wc += (pos > mneg && mask > 0.5f) ? 1.0f : 0.0f;
            }
        }
    }
    __syncthreads();
    if (tx == 0) {
        s_red[ty] = wl;
        s_red[8 + ty] = wm;
        s_red[16 + ty] = wc;
    }
    __syncthreads();
    if (tid == 0) {
        float a = 0.f, b2 = 0.f, c2 = 0.f;
        #pragma unroll
        for (int j = 0; j < 8; j++) { a += s_red[j]; b2 += s_red[8+j]; c2 += s_red[16+j]; }
        atomicAdd(&g_acc[0], a);
        atomicAdd(&g_acc[1], b2);
        atomicAdd(&g_acc[2], c2);
    }
}

// ---------------- kernel 3: hard negatives + grid-pixel loss + epilogue ------
__global__ __launch_bounds__(256) void k_hard(const float* __restrict__ proj,
                                              const int*   __restrict__ offu,
                                              const int*   __restrict__ offv,
                                              const float* __restrict__ valid,
                                              float* __restrict__ out) {
    __shared__ float s_depv[CC];
    __shared__ float s_hsim[NHARD];
    const int tid = threadIdx.x;
    const int tx = tid & 31;
    const int ty = tid >> 5;
    const int b = blockIdx.x >> 8;
    const int p = blockIdx.x & 255;
    const int gh = (p >> 4) * 8;
    const int gw = (p & 15) * 8;
    const int ng = gh*WW + gw;

    s_depv[tid] = g_depGrid[(b*NPOS + p)*CC + tid];
    __syncthreads();

    float pu = proj[b*2*NN + ng];
    float pv = proj[b*2*NN + NN + ng];
    int posu = (int)fminf(fmaxf(pu, 0.0f), (float)(WW-1));
    int posv = (int)fminf(fmaxf(pv, 0.0f), (float)(HH-1));

    const uint4* r[12];
    #pragma unroll
    for (int j = 0; j < 12; j++) {
        int h = ty*12 + j;
        int ou = offu[(b*NHARD + h)*NPOS + p];
        int ov = offv[(b*NHARD + h)*NPOS + p];
        if (ou == 0 && ov == 0) ou = 1;
        int hu = min(max(posu + ou, 0), WW-1);
        int hv = min(max(posv + ov, 0), HH-1);
        r[j] = reinterpret_cast<const uint4*>(g_rgbTh + (size_t)(b*NN + hv*WW + hu)*CC);
    }
    uint4 q[12];
    #pragma unroll
    for (int j = 0; j < 12; j++) q[j] = r[j][tx];

    const float4* dv = reinterpret_cast<const float4*>(s_depv);
    float4 d0 = dv[2*tx];
    float4 d1 = dv[2*tx + 1];
    float acc[12];
    #pragma unroll
    for (int j = 0; j < 12; j++) {
        float2 f0 = __half22float2(*reinterpret_cast<__half2*>(&q[j].x));
        float2 f1 = __half22float2(*reinterpret_cast<__half2*>(&q[j].y));
        float2 f2 = __half22float2(*reinterpret_cast<__half2*>(&q[j].z));
        float2 f3 = __half22float2(*reinterpret_cast<__half2*>(&q[j].w));
        float a = 0.0f;
        a += d0.x*f0.x; a += d0.y*f0.y; a += d0.z*f1.x; a += d0.w*f1.y;
        a += d1.x*f2.x; a += d1.y*f2.y; a += d1.z*f3.x; a += d1.w*f3.y;
        acc[j] = a;
    }
    #pragma unroll
    for (int o = 16; o; o >>= 1) {
        #pragma unroll
        for (int j = 0; j < 12; j++)
            acc[j] += __shfl_xor_sync(0xffffffffu, acc[j], o);
    }
    if (tx == 0) {
        #pragma unroll
        for (int j = 0; j < 12; j++) s_hsim[ty*12 + j] = acc[j];
    }
    __syncthreads();

    if (tid < 32) {
        float v0 = s_hsim[tx];
        float v1 = s_hsim[tx + 32];
        float v2 = s_hsim[tx + 64];
        float m = fmaxf(fmaxf(v0, v1), v2);
        #pragma unroll
        for (int o = 16; o; o >>= 1) m = fmaxf(m, __shfl_xor_sync(0xffffffffu, m, o));
        float se = expf(v0 - m) + expf(v1 - m) + expf(v2 - m);
        #pragma unroll
        for (int o = 16; o; o >>= 1) se += __shfl_xor_sync(0xffffffffu, se, o);
        if (tx == 0) {
            float lse_h = m + logf(se);
            int bp = b*NPOS + p;
            float pos = g_posG[bp];
            float lse0 = g_lseG[bp];
            float mx0 = g_mxG[bp];
            float mm = fmaxf(lse0, lse_h);
            float lse = mm + logf(expf(lse0 - mm) + expf(lse_h - mm));
            float mx = fmaxf(mx0, m);
            float mask = valid[b*NN + ng];
            float lossp = (lse - pos) * mask;
            float corr = (pos > mx && mask > 0.5f) ? 1.0f : 0.0f;
            atomicAdd(&g_acc[0], lossp);
            atomicAdd(&g_acc[1], mask);
            atomicAdd(&g_acc[2], corr);
            __threadfence();
            unsigned t = atomicAdd(&g_done, 1u);
            if (t == (unsigned)(BB*NPOS) - 1u) {
                __threadfence();
                float denom = fmaxf(g_acc[1], 1.0f);
                out[0] = g_acc[0] / denom;
                out[1] = g_acc[2] / denom * 100.0f;
            }
        }
    }
}

// ---------------- launch -------------------------------------------------------
extern "C" void kernel_launch(void* const* d_in, const int* in_sizes, int n_in,
                              void* d_out, int out_size) {
    const float* rgb   = (const float*)d_in[0];
    const float* dep   = (const float*)d_in[1];
    const float* proj  = (const float*)d_in[2];
    const float* valid = (const float*)d_in[3];
    const int*   ridx  = (const int*)d_in[4];
    const int*   offu  = (const int*)d_in[5];
    const int*   offv  = (const int*)d_in[6];
    float* out = (float*)d_out;

    const int smem_norm = (8*36 + 32) * (int)sizeof(float) + 32*ROWQ*16;
    cudaFuncSetAttribute(k_norm_t, cudaFuncAttributeMaxDynamicSharedMemorySize, smem_norm);

    const int smem_main = 32*ROWQ*16*3
                        + (NRAND*33 + 32 + 32 + 8*33) * (int)sizeof(float);
    cudaFuncSetAttribute(k_main, cudaFuncAttributeMaxDynamicSharedMemorySize, smem_main);

    k_norm_t<<<BB*NN/32, 256, smem_norm>>>(rgb);
    k_main<<<BB*NN/32, 256, smem_main>>>(dep, proj, ridx, valid);
    k_hard<<<BB*NPOS, 256>>>(proj, offu, offv, valid, out);
}